// round 1
// baseline (speedup 1.0000x reference)
#include <cuda_runtime.h>
#include <math.h>

#define BB 16
#define NN 100
#define CC 100

// Scratch (no allocation allowed): cost as fp32 (exact w.r.t. reference's fp64 cast),
// assignment, per-batch partial losses.
__device__ float  g_cost[BB * NN * NN];
__device__ int    g_col[BB * NN];
__device__ double g_partial[BB];

// ---------------------------------------------------------------------------
// Kernel 1: cost matrix, fp32 in the reference's exact op order.
// cost[b][q][g] = l1 - (iou - bg_ratio) - probs
// ---------------------------------------------------------------------------
__global__ void cost_kernel(const float* __restrict__ bbox_pred,
                            const float* __restrict__ labels_pred,
                            const float* __restrict__ bbox_gt,
                            const int*   __restrict__ labels_gt)
{
    int b = blockIdx.x;
    __shared__ float4 s_pr[NN];
    __shared__ float4 s_gt[NN];
    __shared__ int    s_lab[NN];
    for (int i = threadIdx.x; i < NN; i += blockDim.x) {
        s_pr[i]  = ((const float4*)bbox_pred)[b * NN + i];
        s_gt[i]  = ((const float4*)bbox_gt)[b * NN + i];
        s_lab[i] = labels_gt[b * NN + i];
    }
    __syncthreads();

    for (int idx = threadIdx.x; idx < NN * NN; idx += blockDim.x) {
        int q = idx / NN;
        int g = idx % NN;
        float4 p = s_pr[q];
        float4 t = s_gt[g];

        float pulx = p.x - 0.5f * p.z, puly = p.y - 0.5f * p.w;
        float pdrx = p.x + 0.5f * p.z, pdry = p.y + 0.5f * p.w;
        float gulx = t.x - 0.5f * t.z, guly = t.y - 0.5f * t.w;
        float gdrx = t.x + 0.5f * t.z, gdry = t.y + 0.5f * t.w;

        float iw = fmaxf(fminf(pdrx, gdrx) - fmaxf(pulx, gulx) + 1.0f, 0.0f);
        float ih = fmaxf(fminf(pdry, gdry) - fmaxf(puly, guly) + 1.0f, 0.0f);
        float inter = iw * ih;

        float pw = fmaxf(pdrx - pulx + 1.0f, 0.0f);
        float ph = fmaxf(pdry - puly + 1.0f, 0.0f);
        float gw = fmaxf(gdrx - gulx + 1.0f, 0.0f);
        float gh = fmaxf(gdry - guly + 1.0f, 0.0f);
        float parea = pw * ph;
        float garea = gw * gh;
        float uni   = parea + garea - inter;
        float iou   = inter / fmaxf(uni, 1e-9f);

        float bw = fmaxf(fmaxf(pdrx, gdrx) - fminf(pulx, gulx) + 1.0f, 0.0f);
        float bh = fmaxf(fmaxf(pdry, gdry) - fminf(puly, guly) + 1.0f, 0.0f);
        float bound = bw * bh;
        float bgr = (bound - uni) / fmaxf(bound, 1e-9f);

        float l1 = fabsf(p.x - t.x) + fabsf(p.y - t.y) +
                   fabsf(p.z - t.z) + fabsf(p.w - t.w);

        float prob = labels_pred[(b * NN + q) * CC + s_lab[g]];

        g_cost[(b * NN + q) * NN + g] = l1 - (iou - bgr) - prob;
    }
}

// ---------------------------------------------------------------------------
// Kernel 2: exact Jonker-Volgenant Hungarian, one warp per batch.
// Replicates the reference numpy algorithm in fp64, including strict-< minv
// updates and first-index argmin tie-breaking. Cost staged in SMEM as fp32
// (lossless: reference widens fp32 -> fp64).
// ---------------------------------------------------------------------------
__global__ void __launch_bounds__(32, 1) hungarian_kernel()
{
    int b    = blockIdx.x;
    int lane = threadIdx.x;   // 32 threads

    __shared__ float  s_cost[NN * NN];      // 40 KB
    __shared__ double u[NN + 1], v[NN + 1], minv[NN + 1];
    __shared__ int    p[NN + 1], way[NN + 1];
    __shared__ unsigned char used[NN + 1];

    const float* gc = g_cost + b * NN * NN;
    for (int i = lane; i < NN * NN; i += 32) s_cost[i] = gc[i];
    for (int j = lane; j <= NN; j += 32) { u[j] = 0.0; v[j] = 0.0; p[j] = 0; way[j] = 0; }
    __syncwarp();

    for (int i = 1; i <= NN; i++) {
        for (int j = lane; j <= NN; j += 32) { minv[j] = 1e300; used[j] = 0; }
        if (lane == 0) p[0] = i;
        __syncwarp();

        int j0 = 0;
        while (true) {
            if (lane == 0) used[j0] = 1;
            __syncwarp();

            int    i0   = p[j0];
            double ui0  = u[i0];
            const float* crow = s_cost + (i0 - 1) * NN;

            // Update minv/way for free columns, track lane-local argmin
            // (scanned in increasing j => first-min kept on exact ties).
            double bestv = 1e300;
            int    bestj = 0;
            for (int j = lane + 1; j <= NN; j += 32) {
                if (!used[j]) {
                    double cur = (double)crow[j - 1] - ui0 - v[j];
                    if (cur < minv[j]) { minv[j] = cur; way[j] = j0; }
                    double m = minv[j];
                    if (m < bestv) { bestv = m; bestj = j; }
                }
            }
            // Warp argmin with lowest-index tie-break (matches np.argmin).
            #pragma unroll
            for (int off = 16; off; off >>= 1) {
                double ov = __shfl_down_sync(0xffffffffu, bestv, off);
                int    oj = __shfl_down_sync(0xffffffffu, bestj, off);
                if (ov < bestv || (ov == bestv && oj < bestj)) { bestv = ov; bestj = oj; }
            }
            double delta = __shfl_sync(0xffffffffu, bestv, 0);
            int    j1    = __shfl_sync(0xffffffffu, bestj, 0);
            __syncwarp();

            // u[p[used]] += delta ; v[used] -= delta ; minv[free] -= delta
            for (int j = lane + 1; j <= NN; j += 32) {
                if (used[j]) { u[p[j]] += delta; v[j] -= delta; }
                else         { minv[j] -= delta; }
            }
            if (lane == 0) { u[p[0]] += delta; v[0] -= delta; }  // column 0 is used
            __syncwarp();

            j0 = j1;
            if (p[j0] == 0) break;
        }

        // Augment along the alternating path (serial, lane 0).
        if (lane == 0) {
            int jj = j0;
            while (jj) { int jn = way[jj]; p[jj] = p[jn]; jj = jn; }
        }
        __syncwarp();
    }

    // ans[p[j]-1] = j-1
    for (int j = lane + 1; j <= NN; j += 32)
        g_col[b * NN + (p[j] - 1)] = j - 1;
}

// ---------------------------------------------------------------------------
// Kernel 3: per-batch losses.
// label: log_softmax(log(clip(p))) => nll = log(sum clip(p)) - log(clip(p_lab))
// reg:   mean |bbox_pred - bbox_gt[col]|
// giou:  mean (iou - bg_ratio) between pred[q] and gt[q] (diagonal!)
// ---------------------------------------------------------------------------
__global__ void loss_kernel(const float* __restrict__ bbox_pred,
                            const float* __restrict__ labels_pred,
                            const float* __restrict__ bbox_gt,
                            const int*   __restrict__ labels_gt)
{
    int b   = blockIdx.x;
    int tid = threadIdx.x;  // 128

    double nll_sum = 0.0, reg_sum = 0.0, giou_sum = 0.0;

    for (int q = tid; q < NN; q += blockDim.x) {
        int cg  = g_col[b * NN + q];
        int lab = labels_gt[b * NN + cg];

        const float* pr = labels_pred + (size_t)(b * NN + q) * CC;
        double se = 0.0;
        float  plab = 0.0f;
        for (int c = 0; c < CC; c++) {
            float pc = fminf(fmaxf(pr[c], 1e-7f), 1.0f - 1e-7f);
            se += (double)pc;
            if (c == lab) plab = pc;
        }
        nll_sum += log(se) - (double)logf(plab);

        float4 p = ((const float4*)bbox_pred)[b * NN + q];
        float4 t = ((const float4*)bbox_gt)[b * NN + cg];
        reg_sum += (double)(fabsf(p.x - t.x) + fabsf(p.y - t.y) +
                            fabsf(p.z - t.z) + fabsf(p.w - t.w));

        // diagonal giou term vs gt[q]
        float4 g = ((const float4*)bbox_gt)[b * NN + q];
        float pulx = p.x - 0.5f * p.z, puly = p.y - 0.5f * p.w;
        float pdrx = p.x + 0.5f * p.z, pdry = p.y + 0.5f * p.w;
        float gulx = g.x - 0.5f * g.z, guly = g.y - 0.5f * g.w;
        float gdrx = g.x + 0.5f * g.z, gdry = g.y + 0.5f * g.w;
        float iw = fmaxf(fminf(pdrx, gdrx) - fmaxf(pulx, gulx) + 1.0f, 0.0f);
        float ih = fmaxf(fminf(pdry, gdry) - fmaxf(puly, guly) + 1.0f, 0.0f);
        float inter = iw * ih;
        float pw = fmaxf(pdrx - pulx + 1.0f, 0.0f);
        float ph = fmaxf(pdry - puly + 1.0f, 0.0f);
        float gw = fmaxf(gdrx - gulx + 1.0f, 0.0f);
        float gh = fmaxf(gdry - guly + 1.0f, 0.0f);
        float uni = pw * ph + gw * gh - inter;
        float iou = inter / fmaxf(uni, 1e-9f);
        float bw = fmaxf(fmaxf(pdrx, gdrx) - fminf(pulx, gulx) + 1.0f, 0.0f);
        float bh = fmaxf(fmaxf(pdry, gdry) - fminf(puly, guly) + 1.0f, 0.0f);
        float bound = bw * bh;
        float bgr = (bound - uni) / fmaxf(bound, 1e-9f);
        giou_sum += (double)(iou - bgr);
    }

    __shared__ double s0[128], s1[128], s2[128];
    s0[tid] = nll_sum; s1[tid] = reg_sum; s2[tid] = giou_sum;
    __syncthreads();
    for (int s = 64; s; s >>= 1) {
        if (tid < s) { s0[tid] += s0[tid + s]; s1[tid] += s1[tid + s]; s2[tid] += s2[tid + s]; }
        __syncthreads();
    }
    if (tid == 0) {
        double per = s0[0] / NN + 5.0 * (s1[0] / (NN * 4.0)) + 2.0 * (s2[0] / NN);
        g_partial[b] = per;
    }
}

__global__ void final_kernel(float* __restrict__ out)
{
    double s = 0.0;
    for (int b = 0; b < BB; b++) s += g_partial[b];
    out[0] = (float)s;
}

// ---------------------------------------------------------------------------
extern "C" void kernel_launch(void* const* d_in, const int* in_sizes, int n_in,
                              void* d_out, int out_size)
{
    const float* bbox_pred   = (const float*)d_in[0];
    const float* labels_pred = (const float*)d_in[1];
    const float* bbox_gt     = (const float*)d_in[2];
    const int*   labels_gt   = (const int*)d_in[3];

    cost_kernel<<<BB, 256>>>(bbox_pred, labels_pred, bbox_gt, labels_gt);
    hungarian_kernel<<<BB, 32>>>();
    loss_kernel<<<BB, 128>>>(bbox_pred, labels_pred, bbox_gt, labels_gt);
    final_kernel<<<1, 1>>>((float*)d_out);
}

// round 2
// speedup vs baseline: 1.6851x; 1.6851x over previous
#include <cuda_runtime.h>
#include <math.h>

#define BB 16
#define NN 100
#define CC 100

__device__ float  g_cost[BB * NN * NN];
__device__ int    g_col[BB * NN];
__device__ double g_partial[BB];

// ---------------------------------------------------------------------------
// Kernel 1: cost matrix, fp32 in the reference's exact op order.
// ---------------------------------------------------------------------------
__global__ void cost_kernel(const float* __restrict__ bbox_pred,
                            const float* __restrict__ labels_pred,
                            const float* __restrict__ bbox_gt,
                            const int*   __restrict__ labels_gt)
{
    int b = blockIdx.x;
    __shared__ float4 s_pr[NN];
    __shared__ float4 s_gt[NN];
    __shared__ int    s_lab[NN];
    for (int i = threadIdx.x; i < NN; i += blockDim.x) {
        s_pr[i]  = ((const float4*)bbox_pred)[b * NN + i];
        s_gt[i]  = ((const float4*)bbox_gt)[b * NN + i];
        s_lab[i] = labels_gt[b * NN + i];
    }
    __syncthreads();

    for (int idx = threadIdx.x; idx < NN * NN; idx += blockDim.x) {
        int q = idx / NN;
        int g = idx % NN;
        float4 p = s_pr[q];
        float4 t = s_gt[g];

        float pulx = p.x - 0.5f * p.z, puly = p.y - 0.5f * p.w;
        float pdrx = p.x + 0.5f * p.z, pdry = p.y + 0.5f * p.w;
        float gulx = t.x - 0.5f * t.z, guly = t.y - 0.5f * t.w;
        float gdrx = t.x + 0.5f * t.z, gdry = t.y + 0.5f * t.w;

        float iw = fmaxf(fminf(pdrx, gdrx) - fmaxf(pulx, gulx) + 1.0f, 0.0f);
        float ih = fmaxf(fminf(pdry, gdry) - fmaxf(puly, guly) + 1.0f, 0.0f);
        float inter = iw * ih;

        float pw = fmaxf(pdrx - pulx + 1.0f, 0.0f);
        float ph = fmaxf(pdry - puly + 1.0f, 0.0f);
        float gw = fmaxf(gdrx - gulx + 1.0f, 0.0f);
        float gh = fmaxf(gdry - guly + 1.0f, 0.0f);
        float uni = pw * ph + gw * gh - inter;
        float iou = inter / fmaxf(uni, 1e-9f);

        float bw = fmaxf(fmaxf(pdrx, gdrx) - fminf(pulx, gulx) + 1.0f, 0.0f);
        float bh = fmaxf(fmaxf(pdry, gdry) - fminf(puly, guly) + 1.0f, 0.0f);
        float bound = bw * bh;
        float bgr = (bound - uni) / fmaxf(bound, 1e-9f);

        float l1 = fabsf(p.x - t.x) + fabsf(p.y - t.y) +
                   fabsf(p.z - t.z) + fabsf(p.w - t.w);

        float prob = labels_pred[(b * NN + q) * CC + s_lab[g]];

        g_cost[(b * NN + q) * NN + g] = l1 - (iou - bgr) - prob;
    }
}

// ---------------------------------------------------------------------------
// Kernel 2: exact JV Hungarian, one warp per batch, register-resident state.
// Each lane owns columns j = 1+lane+32s (s=0..3). minv/v/way-cache/used live
// in registers; u/p/way in shared. Arithmetic is bit-identical fp64 in the
// reference's op order; argmin via 3x REDUX.SYNC.MIN.U32 on a sortable key
// with exact lowest-index tie-break.
// ---------------------------------------------------------------------------
__global__ void __launch_bounds__(32, 1) hungarian_kernel()
{
    const int b    = blockIdx.x;
    const int lane = threadIdx.x;
    const unsigned FULL = 0xffffffffu;

    __shared__ float  sc[NN * NN];     // 40 KB cost (fp32, widened exactly)
    __shared__ double su[NN + 1];      // row duals
    __shared__ int    sp[NN + 1];      // column -> row assignment
    __shared__ int    sway[NN + 1];    // augmenting-path predecessors

    const float* gc = g_cost + b * NN * NN;
    for (int i = lane; i < NN * NN; i += 32) sc[i] = gc[i];
    for (int j = lane; j <= NN; j += 32) { su[j] = 0.0; sp[j] = 0; sway[j] = 0; }
    __syncwarp();

    int  js[4];
    bool valid[4];
    #pragma unroll
    for (int s = 0; s < 4; s++) { js[s] = 1 + lane + 32 * s; valid[s] = (js[s] <= NN); }

    double v[4] = {0.0, 0.0, 0.0, 0.0};    // column duals (persist across rows)

    for (int i = 1; i <= NN; i++) {
        double minv[4] = {INFINITY, INFINITY, INFINITY, INFINITY};
        int    pj[4];                       // cached p[j] for used columns
        unsigned usedm = 0;

        if (lane == 0) sp[0] = i;
        int    j0  = 0;
        int    i0  = i;
        double ui0 = su[i];                 // u[i] (0 until this insertion)

        while (true) {
            // mark used[j0] (owner lane), cache its current row
            #pragma unroll
            for (int s = 0; s < 4; s++)
                if (j0 == js[s]) { usedm |= 1u << s; pj[s] = i0; }

            // scan free columns: update minv/way, track lane-local argmin
            const float* crow = sc + (i0 - 1) * NN;
            double bestv = INFINITY;
            int    bestj = 0x7FFFFFFF;
            #pragma unroll
            for (int s = 0; s < 4; s++) {
                if (valid[s] && !((usedm >> s) & 1u)) {
                    double cur = (double)crow[js[s] - 1] - ui0 - v[s];
                    if (cur < minv[s]) { minv[s] = cur; sway[js[s]] = j0; }
                    if (minv[s] < bestv) { bestv = minv[s]; bestj = js[s]; }
                }
            }

            // warp argmin: sortable-key double, lowest-j tie-break (exact)
            long long bb = __double_as_longlong(bestv);
            unsigned long long kb =
                (unsigned long long)(bb ^ ((bb >> 63) | 0x8000000000000000LL));
            unsigned hi = (unsigned)(kb >> 32);
            unsigned m1 = __reduce_min_sync(FULL, hi);
            unsigned lo = (hi == m1) ? (unsigned)kb : 0xffffffffu;
            unsigned m2 = __reduce_min_sync(FULL, lo);
            unsigned jx = (hi == m1 && (unsigned)kb == m2) ? (unsigned)bestj
                                                           : 0xffffffffu;
            unsigned j1 = __reduce_min_sync(FULL, jx);
            long long kk = (long long)((((unsigned long long)m1) << 32) | m2);
            double delta = __longlong_as_double((kk < 0) ? (kk ^ 0x8000000000000000LL)
                                                         : ~kk);

            // dual updates (exact order: independent +=/-= per element)
            #pragma unroll
            for (int s = 0; s < 4; s++) {
                if (valid[s]) {
                    if ((usedm >> s) & 1u) { su[pj[s]] += delta; v[s] -= delta; }
                    else                   { minv[s] -= delta; }
                }
            }
            if (lane == 0) su[i] += delta;   // u[p[0]] += delta
            __syncwarp();

            int pj1 = sp[j1];
            if (pj1 == 0) { j0 = (int)j1; break; }
            j0  = (int)j1;
            i0  = pj1;
            ui0 = su[i0];
            __syncwarp();
        }

        // augment along alternating path (serial, lane 0)
        __syncwarp();
        if (lane == 0) {
            int jj = j0;
            while (jj) { int jn = sway[jj]; sp[jj] = sp[jn]; jj = jn; }
        }
        __syncwarp();
    }

    for (int j = lane + 1; j <= NN; j += 32)
        g_col[b * NN + (sp[j] - 1)] = j - 1;
}

// ---------------------------------------------------------------------------
// Kernel 3: per-batch losses.
// ---------------------------------------------------------------------------
__global__ void loss_kernel(const float* __restrict__ bbox_pred,
                            const float* __restrict__ labels_pred,
                            const float* __restrict__ bbox_gt,
                            const int*   __restrict__ labels_gt)
{
    int b   = blockIdx.x;
    int tid = threadIdx.x;  // 128

    double nll_sum = 0.0, reg_sum = 0.0, giou_sum = 0.0;

    for (int q = tid; q < NN; q += blockDim.x) {
        int cg  = g_col[b * NN + q];
        int lab = labels_gt[b * NN + cg];

        const float* pr = labels_pred + (size_t)(b * NN + q) * CC;
        double se = 0.0;
        float  plab = 0.0f;
        for (int c = 0; c < CC; c++) {
            float pc = fminf(fmaxf(pr[c], 1e-7f), 1.0f - 1e-7f);
            se += (double)pc;
            if (c == lab) plab = pc;
        }
        nll_sum += log(se) - (double)logf(plab);

        float4 p = ((const float4*)bbox_pred)[b * NN + q];
        float4 t = ((const float4*)bbox_gt)[b * NN + cg];
        reg_sum += (double)(fabsf(p.x - t.x) + fabsf(p.y - t.y) +
                            fabsf(p.z - t.z) + fabsf(p.w - t.w));

        float4 g = ((const float4*)bbox_gt)[b * NN + q];
        float pulx = p.x - 0.5f * p.z, puly = p.y - 0.5f * p.w;
        float pdrx = p.x + 0.5f * p.z, pdry = p.y + 0.5f * p.w;
        float gulx = g.x - 0.5f * g.z, guly = g.y - 0.5f * g.w;
        float gdrx = g.x + 0.5f * g.z, gdry = g.y + 0.5f * g.w;
        float iw = fmaxf(fminf(pdrx, gdrx) - fmaxf(pulx, gulx) + 1.0f, 0.0f);
        float ih = fmaxf(fminf(pdry, gdry) - fmaxf(puly, guly) + 1.0f, 0.0f);
        float inter = iw * ih;
        float pw = fmaxf(pdrx - pulx + 1.0f, 0.0f);
        float ph = fmaxf(pdry - puly + 1.0f, 0.0f);
        float gw = fmaxf(gdrx - gulx + 1.0f, 0.0f);
        float gh = fmaxf(gdry - guly + 1.0f, 0.0f);
        float uni = pw * ph + gw * gh - inter;
        float iou = inter / fmaxf(uni, 1e-9f);
        float bw = fmaxf(fmaxf(pdrx, gdrx) - fminf(pulx, gulx) + 1.0f, 0.0f);
        float bh = fmaxf(fmaxf(pdry, gdry) - fminf(puly, guly) + 1.0f, 0.0f);
        float bound = bw * bh;
        float bgr = (bound - uni) / fmaxf(bound, 1e-9f);
        giou_sum += (double)(iou - bgr);
    }

    __shared__ double s0[128], s1[128], s2[128];
    s0[tid] = nll_sum; s1[tid] = reg_sum; s2[tid] = giou_sum;
    __syncthreads();
    for (int s = 64; s; s >>= 1) {
        if (tid < s) { s0[tid] += s0[tid + s]; s1[tid] += s1[tid + s]; s2[tid] += s2[tid + s]; }
        __syncthreads();
    }
    if (tid == 0) {
        double per = s0[0] / NN + 5.0 * (s1[0] / (NN * 4.0)) + 2.0 * (s2[0] / NN);
        g_partial[b] = per;
    }
}

__global__ void final_kernel(float* __restrict__ out)
{
    double s = 0.0;
    for (int b = 0; b < BB; b++) s += g_partial[b];
    out[0] = (float)s;
}

// ---------------------------------------------------------------------------
extern "C" void kernel_launch(void* const* d_in, const int* in_sizes, int n_in,
                              void* d_out, int out_size)
{
    const float* bbox_pred   = (const float*)d_in[0];
    const float* labels_pred = (const float*)d_in[1];
    const float* bbox_gt     = (const float*)d_in[2];
    const int*   labels_gt   = (const int*)d_in[3];

    cost_kernel<<<BB, 256>>>(bbox_pred, labels_pred, bbox_gt, labels_gt);
    hungarian_kernel<<<BB, 32>>>();
    loss_kernel<<<BB, 128>>>(bbox_pred, labels_pred, bbox_gt, labels_gt);
    final_kernel<<<1, 1>>>((float*)d_out);
}

// round 4
// speedup vs baseline: 1.9155x; 1.1368x over previous
#include <cuda_runtime.h>
#include <math.h>

#define BB 16
#define NN 100
#define CC 100

__device__ float  g_cost[BB * NN * NN];
__device__ int    g_col[BB * NN];
__device__ double g_partial[BB];

// ---------------------------------------------------------------------------
// Kernel 1: cost matrix, fp32 in the reference's exact op order.
// ---------------------------------------------------------------------------
__global__ void cost_kernel(const float* __restrict__ bbox_pred,
                            const float* __restrict__ labels_pred,
                            const float* __restrict__ bbox_gt,
                            const int*   __restrict__ labels_gt)
{
    int b = blockIdx.x;
    __shared__ float4 s_pr[NN];
    __shared__ float4 s_gt[NN];
    __shared__ int    s_lab[NN];
    for (int i = threadIdx.x; i < NN; i += blockDim.x) {
        s_pr[i]  = ((const float4*)bbox_pred)[b * NN + i];
        s_gt[i]  = ((const float4*)bbox_gt)[b * NN + i];
        s_lab[i] = labels_gt[b * NN + i];
    }
    __syncthreads();

    for (int idx = threadIdx.x; idx < NN * NN; idx += blockDim.x) {
        int q = idx / NN;
        int g = idx % NN;
        float4 p = s_pr[q];
        float4 t = s_gt[g];

        float pulx = p.x - 0.5f * p.z, puly = p.y - 0.5f * p.w;
        float pdrx = p.x + 0.5f * p.z, pdry = p.y + 0.5f * p.w;
        float gulx = t.x - 0.5f * t.z, guly = t.y - 0.5f * t.w;
        float gdrx = t.x + 0.5f * t.z, gdry = t.y + 0.5f * t.w;

        float iw = fmaxf(fminf(pdrx, gdrx) - fmaxf(pulx, gulx) + 1.0f, 0.0f);
        float ih = fmaxf(fminf(pdry, gdry) - fmaxf(puly, guly) + 1.0f, 0.0f);
        float inter = iw * ih;

        float pw = fmaxf(pdrx - pulx + 1.0f, 0.0f);
        float ph = fmaxf(pdry - puly + 1.0f, 0.0f);
        float gw = fmaxf(gdrx - gulx + 1.0f, 0.0f);
        float gh = fmaxf(gdry - guly + 1.0f, 0.0f);
        float uni = pw * ph + gw * gh - inter;
        float iou = inter / fmaxf(uni, 1e-9f);

        float bw = fmaxf(fmaxf(pdrx, gdrx) - fminf(pulx, gulx) + 1.0f, 0.0f);
        float bh = fmaxf(fmaxf(pdry, gdry) - fminf(puly, guly) + 1.0f, 0.0f);
        float bound = bw * bh;
        float bgr = (bound - uni) / fmaxf(bound, 1e-9f);

        float l1 = fabsf(p.x - t.x) + fabsf(p.y - t.y) +
                   fabsf(p.z - t.z) + fabsf(p.w - t.w);

        float prob = labels_pred[(b * NN + q) * CC + s_lab[g]];

        g_cost[(b * NN + q) * NN + g] = l1 - (iou - bgr) - prob;
    }
}

// ---------------------------------------------------------------------------
// Sortable-key helpers: unsigned 64-bit key whose ordering == fp64 ordering.
// ---------------------------------------------------------------------------
__device__ __forceinline__ unsigned long long d2key(double d)
{
    long long b = __double_as_longlong(d);
    return (unsigned long long)(b ^ ((b >> 63) | 0x8000000000000000LL));
}
__device__ __forceinline__ double key2d(unsigned long long k)
{
    long long kk = (long long)k;
    return __longlong_as_double((kk < 0) ? (kk ^ 0x8000000000000000LL) : ~kk);
}

// ---------------------------------------------------------------------------
// Kernel 2: exact JV Hungarian, one warp per batch.  Structure identical to
// the passing R2 kernel (static fp32 cost smem, both per-iteration syncwarps,
// lane-0 su[i] update).  Changes vs R2 are register-local only: contiguous
// column->lane mapping (float4 row load) and integer sortable-key tournament
// for the lane-local argmin (exact fp64 ordering, first-index tie-break).
// ---------------------------------------------------------------------------
__global__ void __launch_bounds__(32, 1) hungarian_kernel()
{
    const int b    = blockIdx.x;
    const int lane = threadIdx.x;
    const unsigned FULL = 0xffffffffu;
    const unsigned long long KMAX = ~0ull;

    __shared__ float  sc[NN * NN];     // 40 KB cost (fp32, widened exactly)
    __shared__ double su[NN + 1];      // row duals
    __shared__ int    sp[NN + 1];      // column -> row
    __shared__ int    sway[NN + 1];    // augmenting-path predecessors

    const float* gc = g_cost + b * NN * NN;
    for (int t = lane; t < NN * NN; t += 32) sc[t] = gc[t];
    for (int j = lane; j <= NN; j += 32) { su[j] = 0.0; sp[j] = 0; sway[j] = 0; }
    __syncwarp();

    const bool active = (lane < 25);
    const int  jbase  = 4 * lane + 1;

    double v[4] = {0.0, 0.0, 0.0, 0.0};   // column duals (persist across rows)

    for (int i = 1; i <= NN; i++) {
        double             minv[4];
        unsigned long long mkey[4];
        int                pj[4] = {0, 0, 0, 0};
        #pragma unroll
        for (int s = 0; s < 4; s++) { minv[s] = INFINITY; mkey[s] = KMAX; }
        unsigned usedm = 0;

        if (lane == 0) sp[0] = i;
        int    j0  = 0;
        int    i0  = i;
        double ui0 = su[i];

        while (true) {
            // mark used[j0] (only owner lane matches), cache its row
            #pragma unroll
            for (int s = 0; s < 4; s++)
                if (j0 == jbase + s) { usedm |= 1u << s; mkey[s] = KMAX; pj[s] = i0; }

            // scan free columns of row i0
            unsigned long long bkey = KMAX;
            int                bj   = 0x7FFFFFFF;
            if (active) {
                const float* crow = sc + (i0 - 1) * NN;
                float4 cf = ((const float4*)crow)[lane];
                double c[4] = {(double)cf.x, (double)cf.y, (double)cf.z, (double)cf.w};
                #pragma unroll
                for (int s = 0; s < 4; s++) {
                    if (!((usedm >> s) & 1u)) {
                        double cur = c[s] - ui0 - v[s];
                        unsigned long long ck = d2key(cur);
                        if (ck < mkey[s]) { mkey[s] = ck; minv[s] = cur; sway[jbase + s] = j0; }
                    }
                }
                // 2-level integer tournament, first-index on ties
                unsigned long long k01 = mkey[0]; int s01 = 0;
                if (mkey[1] < k01) { k01 = mkey[1]; s01 = 1; }
                unsigned long long k23 = mkey[2]; int s23 = 2;
                if (mkey[3] < k23) { k23 = mkey[3]; s23 = 3; }
                bkey = k01; int sb = s01;
                if (k23 < k01) { bkey = k23; sb = s23; }
                bj = jbase + sb;
            }

            // warp argmin on (key, j): exact value + lowest-index tie-break
            unsigned hi = (unsigned)(bkey >> 32);
            unsigned m1 = __reduce_min_sync(FULL, hi);
            unsigned lo = (hi == m1) ? (unsigned)bkey : 0xffffffffu;
            unsigned m2 = __reduce_min_sync(FULL, lo);
            unsigned jx = (hi == m1 && (unsigned)bkey == m2) ? (unsigned)bj : 0xffffffffu;
            unsigned j1 = __reduce_min_sync(FULL, jx);
            double delta = key2d((((unsigned long long)m1) << 32) | (unsigned long long)m2);

            // dual updates (independent element-wise ops, exact order)
            if (active) {
                #pragma unroll
                for (int s = 0; s < 4; s++) {
                    if ((usedm >> s) & 1u) {
                        su[pj[s]] += delta;
                        v[s] -= delta;
                    } else {
                        minv[s] -= delta;
                        mkey[s] = d2key(minv[s]);
                    }
                }
            }
            if (lane == 0) su[i] += delta;   // u[p[0]] += delta (p[0] = i)
            __syncwarp();

            int i0n = sp[j1];
            if (i0n == 0) { j0 = (int)j1; break; }
            j0  = (int)j1;
            i0  = i0n;
            ui0 = su[i0];
            __syncwarp();
        }

        // augment (serial, lane 0)
        __syncwarp();
        if (lane == 0) {
            int jj = j0;
            while (jj) { int jn = sway[jj]; sp[jj] = sp[jn]; jj = jn; }
        }
        __syncwarp();
    }

    for (int j = lane + 1; j <= NN; j += 32)
        g_col[b * NN + (sp[j] - 1)] = j - 1;
}

// ---------------------------------------------------------------------------
// Kernel 3: per-batch losses.
// ---------------------------------------------------------------------------
__global__ void loss_kernel(const float* __restrict__ bbox_pred,
                            const float* __restrict__ labels_pred,
                            const float* __restrict__ bbox_gt,
                            const int*   __restrict__ labels_gt)
{
    int b   = blockIdx.x;
    int tid = threadIdx.x;  // 128

    double nll_sum = 0.0, reg_sum = 0.0, giou_sum = 0.0;

    for (int q = tid; q < NN; q += blockDim.x) {
        int cg  = g_col[b * NN + q];
        int lab = labels_gt[b * NN + cg];

        const float* pr = labels_pred + (size_t)(b * NN + q) * CC;
        double se = 0.0;
        float  plab = 0.0f;
        for (int c = 0; c < CC; c++) {
            float pc = fminf(fmaxf(pr[c], 1e-7f), 1.0f - 1e-7f);
            se += (double)pc;
            if (c == lab) plab = pc;
        }
        nll_sum += log(se) - (double)logf(plab);

        float4 p = ((const float4*)bbox_pred)[b * NN + q];
        float4 t = ((const float4*)bbox_gt)[b * NN + cg];
        reg_sum += (double)(fabsf(p.x - t.x) + fabsf(p.y - t.y) +
                            fabsf(p.z - t.z) + fabsf(p.w - t.w));

        float4 g = ((const float4*)bbox_gt)[b * NN + q];
        float pulx = p.x - 0.5f * p.z, puly = p.y - 0.5f * p.w;
        float pdrx = p.x + 0.5f * p.z, pdry = p.y + 0.5f * p.w;
        float gulx = g.x - 0.5f * g.z, guly = g.y - 0.5f * g.w;
        float gdrx = g.x + 0.5f * g.z, gdry = g.y + 0.5f * g.w;
        float iw = fmaxf(fminf(pdrx, gdrx) - fmaxf(pulx, gulx) + 1.0f, 0.0f);
        float ih = fmaxf(fminf(pdry, gdry) - fmaxf(puly, guly) + 1.0f, 0.0f);
        float inter = iw * ih;
        float pw = fmaxf(pdrx - pulx + 1.0f, 0.0f);
        float ph = fmaxf(pdry - puly + 1.0f, 0.0f);
        float gw = fmaxf(gdrx - gulx + 1.0f, 0.0f);
        float gh = fmaxf(gdry - guly + 1.0f, 0.0f);
        float uni = pw * ph + gw * gh - inter;
        float iou = inter / fmaxf(uni, 1e-9f);
        float bw = fmaxf(fmaxf(pdrx, gdrx) - fminf(pulx, gulx) + 1.0f, 0.0f);
        float bh = fmaxf(fmaxf(pdry, gdry) - fminf(puly, guly) + 1.0f, 0.0f);
        float bound = bw * bh;
        float bgr = (bound - uni) / fmaxf(bound, 1e-9f);
        giou_sum += (double)(iou - bgr);
    }

    __shared__ double s0[128], s1[128], s2[128];
    s0[tid] = nll_sum; s1[tid] = reg_sum; s2[tid] = giou_sum;
    __syncthreads();
    for (int s = 64; s; s >>= 1) {
        if (tid < s) { s0[tid] += s0[tid + s]; s1[tid] += s1[tid + s]; s2[tid] += s2[tid + s]; }
        __syncthreads();
    }
    if (tid == 0) {
        double per = s0[0] / NN + 5.0 * (s1[0] / (NN * 4.0)) + 2.0 * (s2[0] / NN);
        g_partial[b] = per;
    }
}

__global__ void final_kernel(float* __restrict__ out)
{
    double s = 0.0;
    for (int b = 0; b < BB; b++) s += g_partial[b];
    out[0] = (float)s;
}

// ---------------------------------------------------------------------------
extern "C" void kernel_launch(void* const* d_in, const int* in_sizes, int n_in,
                              void* d_out, int out_size)
{
    const float* bbox_pred   = (const float*)d_in[0];
    const float* labels_pred = (const float*)d_in[1];
    const float* bbox_gt     = (const float*)d_in[2];
    const int*   labels_gt   = (const int*)d_in[3];

    cost_kernel<<<BB, 256>>>(bbox_pred, labels_pred, bbox_gt, labels_gt);
    hungarian_kernel<<<BB, 32>>>();
    loss_kernel<<<BB, 128>>>(bbox_pred, labels_pred, bbox_gt, labels_gt);
    final_kernel<<<1, 1>>>((float*)d_out);
}

// round 6
// speedup vs baseline: 1.9628x; 1.0247x over previous
#include <cuda_runtime.h>
#include <math.h>

#define BB 16
#define NN 100
#define CC 100

__device__ float  g_cost[BB * NN * NN];
__device__ int    g_col[BB * NN];
__device__ double g_partial[BB];

// ---------------------------------------------------------------------------
// Kernel 1: cost matrix, fp32 in the reference's exact op order.
// ---------------------------------------------------------------------------
__global__ void cost_kernel(const float* __restrict__ bbox_pred,
                            const float* __restrict__ labels_pred,
                            const float* __restrict__ bbox_gt,
                            const int*   __restrict__ labels_gt)
{
    int b = blockIdx.x;
    __shared__ float4 s_pr[NN];
    __shared__ float4 s_gt[NN];
    __shared__ int    s_lab[NN];
    for (int i = threadIdx.x; i < NN; i += blockDim.x) {
        s_pr[i]  = ((const float4*)bbox_pred)[b * NN + i];
        s_gt[i]  = ((const float4*)bbox_gt)[b * NN + i];
        s_lab[i] = labels_gt[b * NN + i];
    }
    __syncthreads();

    for (int idx = threadIdx.x; idx < NN * NN; idx += blockDim.x) {
        int q = idx / NN;
        int g = idx % NN;
        float4 p = s_pr[q];
        float4 t = s_gt[g];

        float pulx = p.x - 0.5f * p.z, puly = p.y - 0.5f * p.w;
        float pdrx = p.x + 0.5f * p.z, pdry = p.y + 0.5f * p.w;
        float gulx = t.x - 0.5f * t.z, guly = t.y - 0.5f * t.w;
        float gdrx = t.x + 0.5f * t.z, gdry = t.y + 0.5f * t.w;

        float iw = fmaxf(fminf(pdrx, gdrx) - fmaxf(pulx, gulx) + 1.0f, 0.0f);
        float ih = fmaxf(fminf(pdry, gdry) - fmaxf(puly, guly) + 1.0f, 0.0f);
        float inter = iw * ih;

        float pw = fmaxf(pdrx - pulx + 1.0f, 0.0f);
        float ph = fmaxf(pdry - puly + 1.0f, 0.0f);
        float gw = fmaxf(gdrx - gulx + 1.0f, 0.0f);
        float gh = fmaxf(gdry - guly + 1.0f, 0.0f);
        float uni = pw * ph + gw * gh - inter;
        float iou = inter / fmaxf(uni, 1e-9f);

        float bw = fmaxf(fmaxf(pdrx, gdrx) - fminf(pulx, gulx) + 1.0f, 0.0f);
        float bh = fmaxf(fmaxf(pdry, gdry) - fminf(puly, guly) + 1.0f, 0.0f);
        float bound = bw * bh;
        float bgr = (bound - uni) / fmaxf(bound, 1e-9f);

        float l1 = fabsf(p.x - t.x) + fabsf(p.y - t.y) +
                   fabsf(p.z - t.z) + fabsf(p.w - t.w);

        float prob = labels_pred[(b * NN + q) * CC + s_lab[g]];

        g_cost[(b * NN + q) * NN + g] = l1 - (iou - bgr) - prob;
    }
}

// ---------------------------------------------------------------------------
// Sortable-key helpers: unsigned 64-bit key whose ordering == fp64 ordering.
// ---------------------------------------------------------------------------
__device__ __forceinline__ unsigned long long d2key(double d)
{
    long long b = __double_as_longlong(d);
    return (unsigned long long)(b ^ ((b >> 63) | 0x8000000000000000LL));
}
__device__ __forceinline__ double key2d(unsigned long long k)
{
    long long kk = (long long)k;
    return __longlong_as_double((kk < 0) ? (kk ^ 0x8000000000000000LL) : ~kk);
}

// ---------------------------------------------------------------------------
// Kernel 2: exact JV Hungarian, one warp per batch.
// R5 + fix: cinfo ({u[sp[j]], sp[j]} cache) is refreshed at row-end for
// used columns AND the break column j0 (all columns whose assignment/dual
// changed). fp64 arithmetic order and tie-breaks bit-identical to numpy.
// ---------------------------------------------------------------------------
__global__ void __launch_bounds__(32, 1) hungarian_kernel()
{
    const int b    = blockIdx.x;
    const int lane = threadIdx.x;
    const unsigned FULL = 0xffffffffu;
    const unsigned long long KMAX = ~0ull;

    __shared__ float   sc[NN * NN];      // 40 KB cost (fp32, widened exactly)
    __shared__ double  su[NN + 1];       // row duals
    __shared__ double2 cinfo[NN + 1];    // per column: .x = u[sp[j]], .y = (bits) sp[j]
    __shared__ int     sp[NN + 1];       // column -> row
    __shared__ int     sway[NN + 1];     // augmenting-path predecessors

    const float* gc = g_cost + b * NN * NN;
    for (int t = lane; t < NN * NN; t += 32) sc[t] = gc[t];
    for (int j = lane; j <= NN; j += 32) {
        su[j] = 0.0; sp[j] = 0; sway[j] = 0;
        cinfo[j] = make_double2(0.0, __longlong_as_double(0LL));
    }
    __syncwarp();

    const bool active = (lane < 25);
    const int  jbase  = 4 * lane + 1;

    double v[4] = {0.0, 0.0, 0.0, 0.0};   // column duals (persist across rows)

    for (int i = 1; i <= NN; i++) {
        double             minv[4];
        unsigned long long mkey[4];
        int                pj[4] = {0, 0, 0, 0};
        #pragma unroll
        for (int s = 0; s < 4; s++) { minv[s] = INFINITY; mkey[s] = KMAX; }
        unsigned usedm = 0;

        int    j0  = 0;
        int    i0  = i;
        double ui0 = 0.0;     // u[i] is provably 0 at insertion time
        double acc = 0.0;     // running sum of deltas == u[i] (lane 0 writes)

        while (true) {
            // mark used[j0] (only owner lane matches), cache its row
            #pragma unroll
            for (int s = 0; s < 4; s++)
                if (j0 == jbase + s) { usedm |= 1u << s; mkey[s] = KMAX; pj[s] = i0; }

            // scan free columns of row i0
            unsigned long long bkey = KMAX;
            int                bj   = 0x7FFFFFFF;
            if (active) {
                const float* crow = sc + (i0 - 1) * NN;
                float4 cf = ((const float4*)crow)[lane];
                double c[4] = {(double)cf.x, (double)cf.y, (double)cf.z, (double)cf.w};
                #pragma unroll
                for (int s = 0; s < 4; s++) {
                    if (!((usedm >> s) & 1u)) {
                        double cur = c[s] - ui0 - v[s];
                        unsigned long long ck = d2key(cur);
                        if (ck < mkey[s]) { mkey[s] = ck; minv[s] = cur; sway[jbase + s] = j0; }
                    }
                }
                // 2-level integer tournament, first-index on ties
                unsigned long long k01 = mkey[0]; int s01 = 0;
                if (mkey[1] < k01) { k01 = mkey[1]; s01 = 1; }
                unsigned long long k23 = mkey[2]; int s23 = 2;
                if (mkey[3] < k23) { k23 = mkey[3]; s23 = 3; }
                bkey = k01; int sb = s01;
                if (k23 < k01) { bkey = k23; sb = s23; }
                bj = jbase + sb;
            }

            // warp argmin on (key, j): exact value + lowest-index tie-break
            unsigned hi = (unsigned)(bkey >> 32);
            unsigned m1 = __reduce_min_sync(FULL, hi);
            unsigned lo = (hi == m1) ? (unsigned)bkey : 0xffffffffu;
            unsigned m2 = __reduce_min_sync(FULL, lo);
            unsigned jx = (hi == m1 && (unsigned)bkey == m2) ? (unsigned)bj : 0xffffffffu;
            unsigned j1 = __reduce_min_sync(FULL, jx);
            double delta = key2d((((unsigned long long)m1) << 32) | (unsigned long long)m2);

            // dual updates (independent element-wise ops, exact order).
            // su is write-only during the run; each address owned by one lane.
            if (active) {
                #pragma unroll
                for (int s = 0; s < 4; s++) {
                    if ((usedm >> s) & 1u) {
                        su[pj[s]] += delta;
                        v[s] -= delta;
                    } else {
                        minv[s] -= delta;
                        mkey[s] = d2key(minv[s]);
                    }
                }
            }
            acc += delta;                 // only lane 0's copy is consumed

            // single LDS.128: {u[sp[j1]], sp[j1]} — frozen during the run
            double2 ci = cinfo[j1];
            int i0n = (int)__double_as_longlong(ci.y);
            if (i0n == 0) { j0 = (int)j1; break; }
            j0  = (int)j1;
            i0  = i0n;
            ui0 = ci.x;
        }

        // augment (serial, lane 0); write back u[i] once
        __syncwarp();
        if (lane == 0) {
            su[i]  = acc;     // == sequence of (0+d1)+d2+... exactly
            sp[0]  = i;
            int jj = j0;
            while (jj) { int jn = sway[jj]; sp[jj] = sp[jn]; jj = jn; }
        }
        __syncwarp();

        // refresh cached {u,row} for every column whose state changed this
        // run: the used columns AND the break column j0 (path terminal).
        if (active) {
            #pragma unroll
            for (int s = 0; s < 4; s++) {
                int jj = jbase + s;
                if (((usedm >> s) & 1u) || (jj == j0)) {
                    int r = sp[jj];
                    cinfo[jj] =
                        make_double2(su[r], __longlong_as_double((long long)r));
                }
            }
        }
        __syncwarp();
    }

    for (int j = lane + 1; j <= NN; j += 32)
        g_col[b * NN + (sp[j] - 1)] = j - 1;
}

// ---------------------------------------------------------------------------
// Kernel 3: per-batch losses.
// ---------------------------------------------------------------------------
__global__ void loss_kernel(const float* __restrict__ bbox_pred,
                            const float* __restrict__ labels_pred,
                            const float* __restrict__ bbox_gt,
                            const int*   __restrict__ labels_gt)
{
    int b   = blockIdx.x;
    int tid = threadIdx.x;  // 128

    double nll_sum = 0.0, reg_sum = 0.0, giou_sum = 0.0;

    for (int q = tid; q < NN; q += blockDim.x) {
        int cg  = g_col[b * NN + q];
        int lab = labels_gt[b * NN + cg];

        const float* pr = labels_pred + (size_t)(b * NN + q) * CC;
        double se = 0.0;
        float  plab = 0.0f;
        for (int c = 0; c < CC; c++) {
            float pc = fminf(fmaxf(pr[c], 1e-7f), 1.0f - 1e-7f);
            se += (double)pc;
            if (c == lab) plab = pc;
        }
        nll_sum += log(se) - (double)logf(plab);

        float4 p = ((const float4*)bbox_pred)[b * NN + q];
        float4 t = ((const float4*)bbox_gt)[b * NN + cg];
        reg_sum += (double)(fabsf(p.x - t.x) + fabsf(p.y - t.y) +
                            fabsf(p.z - t.z) + fabsf(p.w - t.w));

        float4 g = ((const float4*)bbox_gt)[b * NN + q];
        float pulx = p.x - 0.5f * p.z, puly = p.y - 0.5f * p.w;
        float pdrx = p.x + 0.5f * p.z, pdry = p.y + 0.5f * p.w;
        float gulx = g.x - 0.5f * g.z, guly = g.y - 0.5f * g.w;
        float gdrx = g.x + 0.5f * g.z, gdry = g.y + 0.5f * g.w;
        float iw = fmaxf(fminf(pdrx, gdrx) - fmaxf(pulx, gulx) + 1.0f, 0.0f);
        float ih = fmaxf(fminf(pdry, gdry) - fmaxf(puly, guly) + 1.0f, 0.0f);
        float inter = iw * ih;
        float pw = fmaxf(pdrx - pulx + 1.0f, 0.0f);
        float ph = fmaxf(pdry - puly + 1.0f, 0.0f);
        float gw = fmaxf(gdrx - gulx + 1.0f, 0.0f);
        float gh = fmaxf(gdry - guly + 1.0f, 0.0f);
        float uni = pw * ph + gw * gh - inter;
        float iou = inter / fmaxf(uni, 1e-9f);
        float bw = fmaxf(fmaxf(pdrx, gdrx) - fminf(pulx, gulx) + 1.0f, 0.0f);
        float bh = fmaxf(fmaxf(pdry, gdry) - fminf(puly, guly) + 1.0f, 0.0f);
        float bound = bw * bh;
        float bgr = (bound - uni) / fmaxf(bound, 1e-9f);
        giou_sum += (double)(iou - bgr);
    }

    __shared__ double s0[128], s1[128], s2[128];
    s0[tid] = nll_sum; s1[tid] = reg_sum; s2[tid] = giou_sum;
    __syncthreads();
    for (int s = 64; s; s >>= 1) {
        if (tid < s) { s0[tid] += s0[tid + s]; s1[tid] += s1[tid + s]; s2[tid] += s2[tid + s]; }
        __syncthreads();
    }
    if (tid == 0) {
        double per = s0[0] / NN + 5.0 * (s1[0] / (NN * 4.0)) + 2.0 * (s2[0] / NN);
        g_partial[b] = per;
    }
}

__global__ void final_kernel(float* __restrict__ out)
{
    double s = 0.0;
    for (int b = 0; b < BB; b++) s += g_partial[b];
    out[0] = (float)s;
}

// ---------------------------------------------------------------------------
extern "C" void kernel_launch(void* const* d_in, const int* in_sizes, int n_in,
                              void* d_out, int out_size)
{
    const float* bbox_pred   = (const float*)d_in[0];
    const float* labels_pred = (const float*)d_in[1];
    const float* bbox_gt     = (const float*)d_in[2];
    const int*   labels_gt   = (const int*)d_in[3];

    cost_kernel<<<BB, 256>>>(bbox_pred, labels_pred, bbox_gt, labels_gt);
    hungarian_kernel<<<BB, 32>>>();
    loss_kernel<<<BB, 128>>>(bbox_pred, labels_pred, bbox_gt, labels_gt);
    final_kernel<<<1, 1>>>((float*)d_out);
}

// round 7
// speedup vs baseline: 2.0286x; 1.0335x over previous
#include <cuda_runtime.h>
#include <math.h>

#define BB 16
#define NN 100
#define CC 100

__device__ float  g_cost[BB * NN * NN];
__device__ int    g_col[BB * NN];
__device__ double g_partial[BB];

// ---------------------------------------------------------------------------
// Kernel 1: cost matrix, fp32 in the reference's exact op order.
// ---------------------------------------------------------------------------
__global__ void cost_kernel(const float* __restrict__ bbox_pred,
                            const float* __restrict__ labels_pred,
                            const float* __restrict__ bbox_gt,
                            const int*   __restrict__ labels_gt)
{
    int b = blockIdx.x;
    __shared__ float4 s_pr[NN];
    __shared__ float4 s_gt[NN];
    __shared__ int    s_lab[NN];
    for (int i = threadIdx.x; i < NN; i += blockDim.x) {
        s_pr[i]  = ((const float4*)bbox_pred)[b * NN + i];
        s_gt[i]  = ((const float4*)bbox_gt)[b * NN + i];
        s_lab[i] = labels_gt[b * NN + i];
    }
    __syncthreads();

    for (int idx = threadIdx.x; idx < NN * NN; idx += blockDim.x) {
        int q = idx / NN;
        int g = idx % NN;
        float4 p = s_pr[q];
        float4 t = s_gt[g];

        float pulx = p.x - 0.5f * p.z, puly = p.y - 0.5f * p.w;
        float pdrx = p.x + 0.5f * p.z, pdry = p.y + 0.5f * p.w;
        float gulx = t.x - 0.5f * t.z, guly = t.y - 0.5f * t.w;
        float gdrx = t.x + 0.5f * t.z, gdry = t.y + 0.5f * t.w;

        float iw = fmaxf(fminf(pdrx, gdrx) - fmaxf(pulx, gulx) + 1.0f, 0.0f);
        float ih = fmaxf(fminf(pdry, gdry) - fmaxf(puly, guly) + 1.0f, 0.0f);
        float inter = iw * ih;

        float pw = fmaxf(pdrx - pulx + 1.0f, 0.0f);
        float ph = fmaxf(pdry - puly + 1.0f, 0.0f);
        float gw = fmaxf(gdrx - gulx + 1.0f, 0.0f);
        float gh = fmaxf(gdry - guly + 1.0f, 0.0f);
        float uni = pw * ph + gw * gh - inter;
        float iou = inter / fmaxf(uni, 1e-9f);

        float bw = fmaxf(fmaxf(pdrx, gdrx) - fminf(pulx, gulx) + 1.0f, 0.0f);
        float bh = fmaxf(fmaxf(pdry, gdry) - fminf(puly, guly) + 1.0f, 0.0f);
        float bound = bw * bh;
        float bgr = (bound - uni) / fmaxf(bound, 1e-9f);

        float l1 = fabsf(p.x - t.x) + fabsf(p.y - t.y) +
                   fabsf(p.z - t.z) + fabsf(p.w - t.w);

        float prob = labels_pred[(b * NN + q) * CC + s_lab[g]];

        g_cost[(b * NN + q) * NN + g] = l1 - (iou - bgr) - prob;
    }
}

// ---------------------------------------------------------------------------
// Sortable-key helpers: unsigned 64-bit key whose ordering == fp64 ordering.
// ---------------------------------------------------------------------------
__device__ __forceinline__ unsigned long long d2key(double d)
{
    long long b = __double_as_longlong(d);
    return (unsigned long long)(b ^ ((b >> 63) | 0x8000000000000000LL));
}
__device__ __forceinline__ double key2d(unsigned long long k)
{
    long long kk = (long long)k;
    return __longlong_as_double((kk < 0) ? (kk ^ 0x8000000000000000LL) : ~kk);
}

// ---------------------------------------------------------------------------
// Kernel 2: exact JV Hungarian, one warp per batch.
// vs R6: all per-iteration `if (active)` divergence blocks removed. Every
// lane executes the straight-line body; padding lanes (25-31) load a clamped
// in-bounds address and have their keys forced to KMAX (can never win, never
// mark used, never write shared). Algorithm/fp64 order bit-identical to R6.
// ---------------------------------------------------------------------------
__global__ void __launch_bounds__(32, 1) hungarian_kernel()
{
    const int b    = blockIdx.x;
    const int lane = threadIdx.x;
    const unsigned FULL = 0xffffffffu;
    const unsigned long long KMAX = ~0ull;

    __shared__ float   sc[NN * NN];      // 40 KB cost (fp32, widened exactly)
    __shared__ double  su[NN + 1];       // row duals
    __shared__ double2 cinfo[NN + 1];    // per column: .x = u[sp[j]], .y = (bits) sp[j]
    __shared__ int     sp[NN + 1];       // column -> row
    __shared__ int     sway[NN + 1];     // augmenting-path predecessors

    const float* gc = g_cost + b * NN * NN;
    for (int t = lane; t < NN * NN; t += 32) sc[t] = gc[t];
    for (int j = lane; j <= NN; j += 32) {
        su[j] = 0.0; sp[j] = 0; sway[j] = 0;
        cinfo[j] = make_double2(0.0, __longlong_as_double(0LL));
    }
    __syncwarp();

    const int  jbase = 4 * lane + 1;
    // clamped float4 offset: padding lanes re-load lane 24's columns
    const int  coff  = (lane < 25) ? 4 * lane : 96;
    // key poison: padding lanes can never win the argmin
    const unsigned long long pad = (lane < 25) ? 0ull : KMAX;

    double v[4] = {0.0, 0.0, 0.0, 0.0};   // column duals (persist across rows)

    for (int i = 1; i <= NN; i++) {
        double             minv[4];
        unsigned long long mkey[4];
        int                pj[4] = {0, 0, 0, 0};
        #pragma unroll
        for (int s = 0; s < 4; s++) { minv[s] = INFINITY; mkey[s] = KMAX; }
        unsigned usedm = 0;

        int    j0  = 0;
        int    i0  = i;
        double ui0 = 0.0;     // u[i] is provably 0 at insertion time
        double acc = 0.0;     // running sum of deltas == u[i] (lane 0 writes)

        while (true) {
            // mark used[j0] (only owner lane matches; never a padding lane)
            #pragma unroll
            for (int s = 0; s < 4; s++)
                if (j0 == jbase + s) { usedm |= 1u << s; mkey[s] = KMAX; pj[s] = i0; }

            // scan: straight-line, predicated (no divergence envelope)
            const float* crow = sc + (i0 - 1) * NN;
            float4 cf = *(const float4*)(crow + coff);
            double c[4] = {(double)cf.x, (double)cf.y, (double)cf.z, (double)cf.w};
            #pragma unroll
            for (int s = 0; s < 4; s++) {
                if (!((usedm >> s) & 1u)) {
                    double cur = c[s] - ui0 - v[s];
                    unsigned long long ck = d2key(cur) | pad;
                    if (ck < mkey[s]) { mkey[s] = ck; minv[s] = cur; sway[jbase + s] = j0; }
                }
            }
            // 2-level integer tournament, first-index on ties
            unsigned long long k01 = mkey[0]; int s01 = 0;
            if (mkey[1] < k01) { k01 = mkey[1]; s01 = 1; }
            unsigned long long k23 = mkey[2]; int s23 = 2;
            if (mkey[3] < k23) { k23 = mkey[3]; s23 = 3; }
            unsigned long long bkey = k01; int sb = s01;
            if (k23 < k01) { bkey = k23; sb = s23; }
            int bj = jbase + sb;

            // warp argmin on (key, j): exact value + lowest-index tie-break
            unsigned hi = (unsigned)(bkey >> 32);
            unsigned m1 = __reduce_min_sync(FULL, hi);
            unsigned lo = (hi == m1) ? (unsigned)bkey : 0xffffffffu;
            unsigned m2 = __reduce_min_sync(FULL, lo);
            unsigned jx = (hi == m1 && (unsigned)bkey == m2) ? (unsigned)bj : 0xffffffffu;
            unsigned j1 = __reduce_min_sync(FULL, jx);
            double delta = key2d((((unsigned long long)m1) << 32) | (unsigned long long)m2);

            // dual updates, straight-line predicated. su writes only where
            // usedm bit set (never padding lanes); addresses lane-owned.
            #pragma unroll
            for (int s = 0; s < 4; s++) {
                if ((usedm >> s) & 1u) {
                    su[pj[s]] += delta;
                    v[s] -= delta;
                } else {
                    minv[s] -= delta;
                    mkey[s] = d2key(minv[s]) | pad;
                }
            }
            acc += delta;                 // only lane 0's copy is consumed

            // single LDS.128: {u[sp[j1]], sp[j1]} — frozen during the run
            double2 ci = cinfo[j1];
            int i0n = (int)__double_as_longlong(ci.y);
            if (i0n == 0) { j0 = (int)j1; break; }
            j0  = (int)j1;
            i0  = i0n;
            ui0 = ci.x;
        }

        // augment (serial, lane 0); write back u[i] once
        __syncwarp();
        if (lane == 0) {
            su[i]  = acc;     // == sequence of (0+d1)+d2+... exactly
            sp[0]  = i;
            int jj = j0;
            while (jj) { int jn = sway[jj]; sp[jj] = sp[jn]; jj = jn; }
        }
        __syncwarp();

        // refresh cached {u,row} for every column whose state changed this
        // run: used columns AND the break column j0. Guard is always false
        // for padding lanes (usedm=0, jj>NN>=j0), so no OOB access occurs.
        #pragma unroll
        for (int s = 0; s < 4; s++) {
            int jj = jbase + s;
            if (((usedm >> s) & 1u) || (jj == j0)) {
                int r = sp[jj];
                cinfo[jj] = make_double2(su[r], __longlong_as_double((long long)r));
            }
        }
        __syncwarp();
    }

    for (int j = lane + 1; j <= NN; j += 32)
        g_col[b * NN + (sp[j] - 1)] = j - 1;
}

// ---------------------------------------------------------------------------
// Kernel 3: per-batch losses.
// ---------------------------------------------------------------------------
__global__ void loss_kernel(const float* __restrict__ bbox_pred,
                            const float* __restrict__ labels_pred,
                            const float* __restrict__ bbox_gt,
                            const int*   __restrict__ labels_gt)
{
    int b   = blockIdx.x;
    int tid = threadIdx.x;  // 128

    double nll_sum = 0.0, reg_sum = 0.0, giou_sum = 0.0;

    for (int q = tid; q < NN; q += blockDim.x) {
        int cg  = g_col[b * NN + q];
        int lab = labels_gt[b * NN + cg];

        const float* pr = labels_pred + (size_t)(b * NN + q) * CC;
        double se = 0.0;
        float  plab = 0.0f;
        for (int c = 0; c < CC; c++) {
            float pc = fminf(fmaxf(pr[c], 1e-7f), 1.0f - 1e-7f);
            se += (double)pc;
            if (c == lab) plab = pc;
        }
        nll_sum += log(se) - (double)logf(plab);

        float4 p = ((const float4*)bbox_pred)[b * NN + q];
        float4 t = ((const float4*)bbox_gt)[b * NN + cg];
        reg_sum += (double)(fabsf(p.x - t.x) + fabsf(p.y - t.y) +
                            fabsf(p.z - t.z) + fabsf(p.w - t.w));

        float4 g = ((const float4*)bbox_gt)[b * NN + q];
        float pulx = p.x - 0.5f * p.z, puly = p.y - 0.5f * p.w;
        float pdrx = p.x + 0.5f * p.z, pdry = p.y + 0.5f * p.w;
        float gulx = g.x - 0.5f * g.z, guly = g.y - 0.5f * g.w;
        float gdrx = g.x + 0.5f * g.z, gdry = g.y + 0.5f * g.w;
        float iw = fmaxf(fminf(pdrx, gdrx) - fmaxf(pulx, gulx) + 1.0f, 0.0f);
        float ih = fmaxf(fminf(pdry, gdry) - fmaxf(puly, guly) + 1.0f, 0.0f);
        float inter = iw * ih;
        float pw = fmaxf(pdrx - pulx + 1.0f, 0.0f);
        float ph = fmaxf(pdry - puly + 1.0f, 0.0f);
        float gw = fmaxf(gdrx - gulx + 1.0f, 0.0f);
        float gh = fmaxf(gdry - guly + 1.0f, 0.0f);
        float uni = pw * ph + gw * gh - inter;
        float iou = inter / fmaxf(uni, 1e-9f);
        float bw = fmaxf(fmaxf(pdrx, gdrx) - fminf(pulx, gulx) + 1.0f, 0.0f);
        float bh = fmaxf(fmaxf(pdry, gdry) - fminf(puly, guly) + 1.0f, 0.0f);
        float bound = bw * bh;
        float bgr = (bound - uni) / fmaxf(bound, 1e-9f);
        giou_sum += (double)(iou - bgr);
    }

    __shared__ double s0[128], s1[128], s2[128];
    s0[tid] = nll_sum; s1[tid] = reg_sum; s2[tid] = giou_sum;
    __syncthreads();
    for (int s = 64; s; s >>= 1) {
        if (tid < s) { s0[tid] += s0[tid + s]; s1[tid] += s1[tid + s]; s2[tid] += s2[tid + s]; }
        __syncthreads();
    }
    if (tid == 0) {
        double per = s0[0] / NN + 5.0 * (s1[0] / (NN * 4.0)) + 2.0 * (s2[0] / NN);
        g_partial[b] = per;
    }
}

__global__ void final_kernel(float* __restrict__ out)
{
    double s = 0.0;
    for (int b = 0; b < BB; b++) s += g_partial[b];
    out[0] = (float)s;
}

// ---------------------------------------------------------------------------
extern "C" void kernel_launch(void* const* d_in, const int* in_sizes, int n_in,
                              void* d_out, int out_size)
{
    const float* bbox_pred   = (const float*)d_in[0];
    const float* labels_pred = (const float*)d_in[1];
    const float* bbox_gt     = (const float*)d_in[2];
    const int*   labels_gt   = (const int*)d_in[3];

    cost_kernel<<<BB, 256>>>(bbox_pred, labels_pred, bbox_gt, labels_gt);
    hungarian_kernel<<<BB, 32>>>();
    loss_kernel<<<BB, 128>>>(bbox_pred, labels_pred, bbox_gt, labels_gt);
    final_kernel<<<1, 1>>>((float*)d_out);
}

// round 8
// speedup vs baseline: 2.3444x; 1.1557x over previous
#include <cuda_runtime.h>
#include <math.h>

#define BB 16
#define NN 100
#define CC 100

__device__ float  g_cost[BB * NN * NN];
__device__ int    g_col[BB * NN];
__device__ double g_partial[BB];

// ---------------------------------------------------------------------------
// Kernel 1: cost matrix, fp32 in the reference's exact op order.
// ---------------------------------------------------------------------------
__global__ void cost_kernel(const float* __restrict__ bbox_pred,
                            const float* __restrict__ labels_pred,
                            const float* __restrict__ bbox_gt,
                            const int*   __restrict__ labels_gt)
{
    int b = blockIdx.x;
    __shared__ float4 s_pr[NN];
    __shared__ float4 s_gt[NN];
    __shared__ int    s_lab[NN];
    for (int i = threadIdx.x; i < NN; i += blockDim.x) {
        s_pr[i]  = ((const float4*)bbox_pred)[b * NN + i];
        s_gt[i]  = ((const float4*)bbox_gt)[b * NN + i];
        s_lab[i] = labels_gt[b * NN + i];
    }
    __syncthreads();

    for (int idx = threadIdx.x; idx < NN * NN; idx += blockDim.x) {
        int q = idx / NN;
        int g = idx % NN;
        float4 p = s_pr[q];
        float4 t = s_gt[g];

        float pulx = p.x - 0.5f * p.z, puly = p.y - 0.5f * p.w;
        float pdrx = p.x + 0.5f * p.z, pdry = p.y + 0.5f * p.w;
        float gulx = t.x - 0.5f * t.z, guly = t.y - 0.5f * t.w;
        float gdrx = t.x + 0.5f * t.z, gdry = t.y + 0.5f * t.w;

        float iw = fmaxf(fminf(pdrx, gdrx) - fmaxf(pulx, gulx) + 1.0f, 0.0f);
        float ih = fmaxf(fminf(pdry, gdry) - fmaxf(puly, guly) + 1.0f, 0.0f);
        float inter = iw * ih;

        float pw = fmaxf(pdrx - pulx + 1.0f, 0.0f);
        float ph = fmaxf(pdry - puly + 1.0f, 0.0f);
        float gw = fmaxf(gdrx - gulx + 1.0f, 0.0f);
        float gh = fmaxf(gdry - guly + 1.0f, 0.0f);
        float uni = pw * ph + gw * gh - inter;
        float iou = inter / fmaxf(uni, 1e-9f);

        float bw = fmaxf(fmaxf(pdrx, gdrx) - fminf(pulx, gulx) + 1.0f, 0.0f);
        float bh = fmaxf(fmaxf(pdry, gdry) - fminf(puly, guly) + 1.0f, 0.0f);
        float bound = bw * bh;
        float bgr = (bound - uni) / fmaxf(bound, 1e-9f);

        float l1 = fabsf(p.x - t.x) + fabsf(p.y - t.y) +
                   fabsf(p.z - t.z) + fabsf(p.w - t.w);

        float prob = labels_pred[(b * NN + q) * CC + s_lab[g]];

        g_cost[(b * NN + q) * NN + g] = l1 - (iou - bgr) - prob;
    }
}

// ---------------------------------------------------------------------------
// Sortable-key helpers: unsigned 64-bit key whose ordering == fp64 ordering.
// ---------------------------------------------------------------------------
__device__ __forceinline__ unsigned long long d2key(double d)
{
    long long b = __double_as_longlong(d);
    return (unsigned long long)(b ^ ((b >> 63) | 0x8000000000000000LL));
}
__device__ __forceinline__ double key2d(unsigned long long k)
{
    long long kk = (long long)k;
    return __longlong_as_double((kk < 0) ? (kk ^ 0x8000000000000000LL) : ~kk);
}

// ---------------------------------------------------------------------------
// Kernel 2: exact JV Hungarian, one warp per batch.
// vs R7: JV column-reduction init. v[j] = min_i c[i][j]; greedy-assign each
// column's argmin row if free (~63% of rows). The augmenting Dijkstra (body
// identical to the validated R7 loop, with t=ui0+v hoisted off the critical
// path) runs only for the remaining unassigned rows, from the dual-feasible
// start (u=0, v=colmin; reduced costs >= 0, greedy pairs == 0). For
// continuous random costs the optimum is unique, so the final assignment --
// and hence the loss -- is identical to the reference's.
// ---------------------------------------------------------------------------
__global__ void __launch_bounds__(32, 1) hungarian_kernel()
{
    const int b    = blockIdx.x;
    const int lane = threadIdx.x;
    const unsigned FULL = 0xffffffffu;
    const unsigned long long KMAX = ~0ull;

    __shared__ float   sc[NN * NN];      // 40 KB cost (fp32, widened exactly)
    __shared__ double  su[NN + 1];       // row duals
    __shared__ double2 cinfo[NN + 1];    // per column: .x = u[sp[j]], .y = (bits) sp[j]
    __shared__ int     sp[NN + 1];       // column -> row
    __shared__ int     sway[NN + 1];     // augmenting-path predecessors
    __shared__ int     sargmin[NN + 1];  // column-reduction argmin rows
    __shared__ unsigned char srowass[NN + 1];  // greedy row-assigned flags

    const float* gc = g_cost + b * NN * NN;
    for (int t = lane; t < NN * NN; t += 32) sc[t] = gc[t];
    for (int j = lane; j <= NN; j += 32) {
        su[j] = 0.0; sp[j] = 0; sway[j] = 0; srowass[j] = 0;
    }
    __syncwarp();

    const int  jbase = 4 * lane + 1;
    const int  coff  = (lane < 25) ? 4 * lane : 96;   // clamped float4 offset
    const unsigned long long pad = (lane < 25) ? 0ull : KMAX;  // key poison

    // ---- column reduction: v[j] = min_i c[i][j], first-argmin row ----
    float vminf[4] = {INFINITY, INFINITY, INFINITY, INFINITY};
    int   rmin[4]  = {1, 1, 1, 1};
    for (int r = 0; r < NN; r++) {
        float4 cf = *(const float4*)(sc + r * NN + coff);
        float cv[4] = {cf.x, cf.y, cf.z, cf.w};
        #pragma unroll
        for (int s = 0; s < 4; s++)
            if (cv[s] < vminf[s]) { vminf[s] = cv[s]; rmin[s] = r + 1; }
    }
    if (lane < 25) {
        #pragma unroll
        for (int s = 0; s < 4; s++) sargmin[jbase + s] = rmin[s];
    }
    __syncwarp();

    // ---- greedy assignment (serial, lane 0) ----
    if (lane == 0) {
        for (int j = 1; j <= NN; j++) {
            int r = sargmin[j];
            if (!srowass[r]) { srowass[r] = 1; sp[j] = r; }
        }
    }
    __syncwarp();
    if (lane < 25) {
        #pragma unroll
        for (int s = 0; s < 4; s++) {
            int jj = jbase + s;
            cinfo[jj] = make_double2(0.0, __longlong_as_double((long long)sp[jj]));
        }
    }
    __syncwarp();

    double v[4];
    #pragma unroll
    for (int s = 0; s < 4; s++) v[s] = (double)vminf[s];  // exact widen

    // ---- augmenting Dijkstra for unassigned rows only ----
    for (int i = 1; i <= NN; i++) {
        if (srowass[i]) continue;      // uniform branch (shared broadcast)

        double             minv[4];
        unsigned long long mkey[4];
        int                pj[4] = {0, 0, 0, 0};
        double             t4[4];
        #pragma unroll
        for (int s = 0; s < 4; s++) {
            minv[s] = INFINITY; mkey[s] = KMAX;
            t4[s] = v[s];              // ui0 = u[i] = 0 at insertion
        }
        unsigned usedm = 0;

        int    j0  = 0;
        int    i0  = i;
        double acc = 0.0;              // running sum of deltas == u[i]

        while (true) {
            // mark used[j0] (only owner lane matches; never a padding lane)
            #pragma unroll
            for (int s = 0; s < 4; s++)
                if (j0 == jbase + s) { usedm |= 1u << s; mkey[s] = KMAX; pj[s] = i0; }

            // scan: straight-line, predicated
            const float* crow = sc + (i0 - 1) * NN;
            float4 cf = *(const float4*)(crow + coff);
            double c[4] = {(double)cf.x, (double)cf.y, (double)cf.z, (double)cf.w};
            #pragma unroll
            for (int s = 0; s < 4; s++) {
                if (!((usedm >> s) & 1u)) {
                    double cur = c[s] - t4[s];          // t4 = u[i0] + v[s]
                    unsigned long long ck = d2key(cur) | pad;
                    if (ck < mkey[s]) { mkey[s] = ck; minv[s] = cur; sway[jbase + s] = j0; }
                }
            }
            // 2-level integer tournament, first-index on ties
            unsigned long long k01 = mkey[0]; int s01 = 0;
            if (mkey[1] < k01) { k01 = mkey[1]; s01 = 1; }
            unsigned long long k23 = mkey[2]; int s23 = 2;
            if (mkey[3] < k23) { k23 = mkey[3]; s23 = 3; }
            unsigned long long bkey = k01; int sb = s01;
            if (k23 < k01) { bkey = k23; sb = s23; }
            int bj = jbase + sb;

            // warp argmin on (key, j): exact value + lowest-index tie-break
            unsigned hi = (unsigned)(bkey >> 32);
            unsigned m1 = __reduce_min_sync(FULL, hi);
            unsigned lo = (hi == m1) ? (unsigned)bkey : 0xffffffffu;
            unsigned m2 = __reduce_min_sync(FULL, lo);
            unsigned jx = (hi == m1 && (unsigned)bkey == m2) ? (unsigned)bj : 0xffffffffu;
            unsigned j1 = __reduce_min_sync(FULL, jx);
            double delta = key2d((((unsigned long long)m1) << 32) | (unsigned long long)m2);

            // dual updates (su addresses lane-owned; never padding lanes)
            #pragma unroll
            for (int s = 0; s < 4; s++) {
                if ((usedm >> s) & 1u) {
                    su[pj[s]] += delta;
                    v[s] -= delta;
                } else {
                    minv[s] -= delta;
                    mkey[s] = d2key(minv[s]) | pad;
                }
            }
            acc += delta;

            // single LDS.128: {u[sp[j1]], sp[j1]} — frozen during the run
            double2 ci = cinfo[j1];
            int i0n = (int)__double_as_longlong(ci.y);
            if (i0n == 0) { j0 = (int)j1; break; }
            j0 = (int)j1;
            i0 = i0n;
            // hoisted t for next iteration (off the LDS critical path)
            #pragma unroll
            for (int s = 0; s < 4; s++) t4[s] = ci.x + v[s];
        }

        // augment (serial, lane 0); write back u[i] once
        __syncwarp();
        if (lane == 0) {
            su[i]  = acc;
            sp[0]  = i;
            int jj = j0;
            while (jj) { int jn = sway[jj]; sp[jj] = sp[jn]; jj = jn; }
        }
        __syncwarp();

        // refresh cached {u,row} for used columns AND the break column j0
        #pragma unroll
        for (int s = 0; s < 4; s++) {
            int jj = jbase + s;
            if (((usedm >> s) & 1u) || (jj == j0)) {
                int r = sp[jj];
                cinfo[jj] = make_double2(su[r], __longlong_as_double((long long)r));
            }
        }
        __syncwarp();
    }

    for (int j = lane + 1; j <= NN; j += 32)
        g_col[b * NN + (sp[j] - 1)] = j - 1;
}

// ---------------------------------------------------------------------------
// Kernel 3: per-batch losses.
// ---------------------------------------------------------------------------
__global__ void loss_kernel(const float* __restrict__ bbox_pred,
                            const float* __restrict__ labels_pred,
                            const float* __restrict__ bbox_gt,
                            const int*   __restrict__ labels_gt)
{
    int b   = blockIdx.x;
    int tid = threadIdx.x;  // 128

    double nll_sum = 0.0, reg_sum = 0.0, giou_sum = 0.0;

    for (int q = tid; q < NN; q += blockDim.x) {
        int cg  = g_col[b * NN + q];
        int lab = labels_gt[b * NN + cg];

        const float* pr = labels_pred + (size_t)(b * NN + q) * CC;
        double se = 0.0;
        float  plab = 0.0f;
        for (int c = 0; c < CC; c++) {
            float pc = fminf(fmaxf(pr[c], 1e-7f), 1.0f - 1e-7f);
            se += (double)pc;
            if (c == lab) plab = pc;
        }
        nll_sum += log(se) - (double)logf(plab);

        float4 p = ((const float4*)bbox_pred)[b * NN + q];
        float4 t = ((const float4*)bbox_gt)[b * NN + cg];
        reg_sum += (double)(fabsf(p.x - t.x) + fabsf(p.y - t.y) +
                            fabsf(p.z - t.z) + fabsf(p.w - t.w));

        float4 g = ((const float4*)bbox_gt)[b * NN + q];
        float pulx = p.x - 0.5f * p.z, puly = p.y - 0.5f * p.w;
        float pdrx = p.x + 0.5f * p.z, pdry = p.y + 0.5f * p.w;
        float gulx = g.x - 0.5f * g.z, guly = g.y - 0.5f * g.w;
        float gdrx = g.x + 0.5f * g.z, gdry = g.y + 0.5f * g.w;
        float iw = fmaxf(fminf(pdrx, gdrx) - fmaxf(pulx, gulx) + 1.0f, 0.0f);
        float ih = fmaxf(fminf(pdry, gdry) - fmaxf(puly, guly) + 1.0f, 0.0f);
        float inter = iw * ih;
        float pw = fmaxf(pdrx - pulx + 1.0f, 0.0f);
        float ph = fmaxf(pdry - puly + 1.0f, 0.0f);
        float gw = fmaxf(gdrx - gulx + 1.0f, 0.0f);
        float gh = fmaxf(gdry - guly + 1.0f, 0.0f);
        float uni = pw * ph + gw * gh - inter;
        float iou = inter / fmaxf(uni, 1e-9f);
        float bw = fmaxf(fmaxf(pdrx, gdrx) - fminf(pulx, gulx) + 1.0f, 0.0f);
        float bh = fmaxf(fmaxf(pdry, gdry) - fminf(puly, guly) + 1.0f, 0.0f);
        float bound = bw * bh;
        float bgr = (bound - uni) / fmaxf(bound, 1e-9f);
        giou_sum += (double)(iou - bgr);
    }

    __shared__ double s0[128], s1[128], s2[128];
    s0[tid] = nll_sum; s1[tid] = reg_sum; s2[tid] = giou_sum;
    __syncthreads();
    for (int s = 64; s; s >>= 1) {
        if (tid < s) { s0[tid] += s0[tid + s]; s1[tid] += s1[tid + s]; s2[tid] += s2[tid + s]; }
        __syncthreads();
    }
    if (tid == 0) {
        double per = s0[0] / NN + 5.0 * (s1[0] / (NN * 4.0)) + 2.0 * (s2[0] / NN);
        g_partial[b] = per;
    }
}

__global__ void final_kernel(float* __restrict__ out)
{
    double s = 0.0;
    for (int b = 0; b < BB; b++) s += g_partial[b];
    out[0] = (float)s;
}

// ---------------------------------------------------------------------------
extern "C" void kernel_launch(void* const* d_in, const int* in_sizes, int n_in,
                              void* d_out, int out_size)
{
    const float* bbox_pred   = (const float*)d_in[0];
    const float* labels_pred = (const float*)d_in[1];
    const float* bbox_gt     = (const float*)d_in[2];
    const int*   labels_gt   = (const int*)d_in[3];

    cost_kernel<<<BB, 256>>>(bbox_pred, labels_pred, bbox_gt, labels_gt);
    hungarian_kernel<<<BB, 32>>>();
    loss_kernel<<<BB, 128>>>(bbox_pred, labels_pred, bbox_gt, labels_gt);
    final_kernel<<<1, 1>>>((float*)d_out);
}

// round 9
// speedup vs baseline: 2.3485x; 1.0017x over previous
#include <cuda_runtime.h>
#include <math.h>

#define BB 16
#define NN 100
#define CC 100

__device__ float  g_cost[BB * NN * NN];
__device__ int    g_col[BB * NN];
__device__ double g_partial[BB];

// ---------------------------------------------------------------------------
// Kernel 1: cost matrix, fp32 in the reference's exact op order.
// ---------------------------------------------------------------------------
__global__ void cost_kernel(const float* __restrict__ bbox_pred,
                            const float* __restrict__ labels_pred,
                            const float* __restrict__ bbox_gt,
                            const int*   __restrict__ labels_gt)
{
    int b = blockIdx.x;
    __shared__ float4 s_pr[NN];
    __shared__ float4 s_gt[NN];
    __shared__ int    s_lab[NN];
    for (int i = threadIdx.x; i < NN; i += blockDim.x) {
        s_pr[i]  = ((const float4*)bbox_pred)[b * NN + i];
        s_gt[i]  = ((const float4*)bbox_gt)[b * NN + i];
        s_lab[i] = labels_gt[b * NN + i];
    }
    __syncthreads();

    for (int idx = threadIdx.x; idx < NN * NN; idx += blockDim.x) {
        int q = idx / NN;
        int g = idx % NN;
        float4 p = s_pr[q];
        float4 t = s_gt[g];

        float pulx = p.x - 0.5f * p.z, puly = p.y - 0.5f * p.w;
        float pdrx = p.x + 0.5f * p.z, pdry = p.y + 0.5f * p.w;
        float gulx = t.x - 0.5f * t.z, guly = t.y - 0.5f * t.w;
        float gdrx = t.x + 0.5f * t.z, gdry = t.y + 0.5f * t.w;

        float iw = fmaxf(fminf(pdrx, gdrx) - fmaxf(pulx, gulx) + 1.0f, 0.0f);
        float ih = fmaxf(fminf(pdry, gdry) - fmaxf(puly, guly) + 1.0f, 0.0f);
        float inter = iw * ih;

        float pw = fmaxf(pdrx - pulx + 1.0f, 0.0f);
        float ph = fmaxf(pdry - puly + 1.0f, 0.0f);
        float gw = fmaxf(gdrx - gulx + 1.0f, 0.0f);
        float gh = fmaxf(gdry - guly + 1.0f, 0.0f);
        float uni = pw * ph + gw * gh - inter;
        float iou = inter / fmaxf(uni, 1e-9f);

        float bw = fmaxf(fmaxf(pdrx, gdrx) - fminf(pulx, gulx) + 1.0f, 0.0f);
        float bh = fmaxf(fmaxf(pdry, gdry) - fminf(puly, guly) + 1.0f, 0.0f);
        float bound = bw * bh;
        float bgr = (bound - uni) / fmaxf(bound, 1e-9f);

        float l1 = fabsf(p.x - t.x) + fabsf(p.y - t.y) +
                   fabsf(p.z - t.z) + fabsf(p.w - t.w);

        float prob = labels_pred[(b * NN + q) * CC + s_lab[g]];

        g_cost[(b * NN + q) * NN + g] = l1 - (iou - bgr) - prob;
    }
}

// ---------------------------------------------------------------------------
// Sortable-key helper: unsigned 64-bit key whose ordering == fp64 ordering.
// ---------------------------------------------------------------------------
__device__ __forceinline__ unsigned long long d2key(double d)
{
    long long b = __double_as_longlong(d);
    return (unsigned long long)(b ^ ((b >> 63) | 0x8000000000000000LL));
}

// ---------------------------------------------------------------------------
// Kernel 2: exact JV Hungarian, one warp per batch.
// vs R8: warp argmin is 2 REDUX (hi32 exact; then lo-top-25-bits packed with
// the 7-bit column index). Value resolved to ~2^-45 relative; ties at that
// level break by smallest j. delta = the chosen column's EXACT fp64 minv,
// fetched via shfl from the owner lane (off the j1->LDS critical path).
// ---------------------------------------------------------------------------
__global__ void __launch_bounds__(32, 1) hungarian_kernel()
{
    const int b    = blockIdx.x;
    const int lane = threadIdx.x;
    const unsigned FULL = 0xffffffffu;
    const unsigned long long KMAX = ~0ull;

    __shared__ float   sc[NN * NN];      // 40 KB cost (fp32, widened exactly)
    __shared__ double  su[NN + 1];       // row duals
    __shared__ double2 cinfo[NN + 1];    // per column: .x = u[sp[j]], .y = (bits) sp[j]
    __shared__ int     sp[NN + 1];       // column -> row
    __shared__ int     sway[NN + 1];     // augmenting-path predecessors
    __shared__ int     sargmin[NN + 1];  // column-reduction argmin rows
    __shared__ unsigned char srowass[NN + 1];  // greedy row-assigned flags

    const float* gc = g_cost + b * NN * NN;
    for (int t = lane; t < NN * NN; t += 32) sc[t] = gc[t];
    for (int j = lane; j <= NN; j += 32) {
        su[j] = 0.0; sp[j] = 0; sway[j] = 0; srowass[j] = 0;
    }
    __syncwarp();

    const int  jbase = 4 * lane + 1;
    const int  coff  = (lane < 25) ? 4 * lane : 96;   // clamped float4 offset
    const unsigned long long pad = (lane < 25) ? 0ull : KMAX;  // key poison

    // ---- column reduction: v[j] = min_i c[i][j], first-argmin row ----
    float vminf[4] = {INFINITY, INFINITY, INFINITY, INFINITY};
    int   rmin[4]  = {1, 1, 1, 1};
    for (int r = 0; r < NN; r++) {
        float4 cf = *(const float4*)(sc + r * NN + coff);
        float cv[4] = {cf.x, cf.y, cf.z, cf.w};
        #pragma unroll
        for (int s = 0; s < 4; s++)
            if (cv[s] < vminf[s]) { vminf[s] = cv[s]; rmin[s] = r + 1; }
    }
    if (lane < 25) {
        #pragma unroll
        for (int s = 0; s < 4; s++) sargmin[jbase + s] = rmin[s];
    }
    __syncwarp();

    // ---- greedy assignment (serial, lane 0) ----
    if (lane == 0) {
        for (int j = 1; j <= NN; j++) {
            int r = sargmin[j];
            if (!srowass[r]) { srowass[r] = 1; sp[j] = r; }
        }
    }
    __syncwarp();
    if (lane < 25) {
        #pragma unroll
        for (int s = 0; s < 4; s++) {
            int jj = jbase + s;
            cinfo[jj] = make_double2(0.0, __longlong_as_double((long long)sp[jj]));
        }
    }
    __syncwarp();

    double v[4];
    #pragma unroll
    for (int s = 0; s < 4; s++) v[s] = (double)vminf[s];  // exact widen

    // ---- augmenting Dijkstra for unassigned rows only ----
    for (int i = 1; i <= NN; i++) {
        if (srowass[i]) continue;      // uniform branch (shared broadcast)

        double             minv[4];
        unsigned long long mkey[4];
        int                pj[4] = {0, 0, 0, 0};
        double             t4[4];
        #pragma unroll
        for (int s = 0; s < 4; s++) {
            minv[s] = INFINITY; mkey[s] = KMAX;
            t4[s] = v[s];              // ui0 = u[i] = 0 at insertion
        }
        unsigned usedm = 0;

        int    j0  = 0;
        int    i0  = i;
        double acc = 0.0;              // running sum of deltas == u[i]

        while (true) {
            // mark used[j0] (only owner lane matches; never a padding lane)
            #pragma unroll
            for (int s = 0; s < 4; s++)
                if (j0 == jbase + s) { usedm |= 1u << s; mkey[s] = KMAX; pj[s] = i0; }

            // scan: straight-line, predicated
            const float* crow = sc + (i0 - 1) * NN;
            float4 cf = *(const float4*)(crow + coff);
            double c[4] = {(double)cf.x, (double)cf.y, (double)cf.z, (double)cf.w};
            #pragma unroll
            for (int s = 0; s < 4; s++) {
                if (!((usedm >> s) & 1u)) {
                    double cur = c[s] - t4[s];          // t4 = u[i0] + v[s]
                    unsigned long long ck = d2key(cur) | pad;
                    if (ck < mkey[s]) { mkey[s] = ck; minv[s] = cur; sway[jbase + s] = j0; }
                }
            }
            // 2-level integer tournament, first-index on ties
            unsigned long long k01 = mkey[0]; int s01 = 0;
            if (mkey[1] < k01) { k01 = mkey[1]; s01 = 1; }
            unsigned long long k23 = mkey[2]; int s23 = 2;
            if (mkey[3] < k23) { k23 = mkey[3]; s23 = 3; }
            unsigned long long bkey = k01; int sb = s01;
            if (k23 < k01) { bkey = k23; sb = s23; }
            int bj = jbase + sb;

            // warp argmin, 2 REDUX: hi exact, then (lo top-25 bits | j).
            unsigned hi = (unsigned)(bkey >> 32);
            unsigned m1 = __reduce_min_sync(FULL, hi);
            unsigned p  = (hi == m1)
                        ? (((unsigned)bkey & 0xFFFFFF80u) | (unsigned)bj)
                        : 0xFFFFFFFFu;
            unsigned m2 = __reduce_min_sync(FULL, p);
            int j1 = (int)(m2 & 0x7Fu);

            // exact delta: shfl the winner column's fp64 minv from its owner
            int sidx  = (j1 - 1) & 3;
            int owner = (j1 - 1) >> 2;
            double m01s = (sidx & 1) ? minv[1] : minv[0];
            double m23s = (sidx & 1) ? minv[3] : minv[2];
            double selv = (sidx & 2) ? m23s : m01s;
            double delta = __shfl_sync(FULL, selv, owner);

            // dual updates (su addresses lane-owned; never padding lanes)
            #pragma unroll
            for (int s = 0; s < 4; s++) {
                if ((usedm >> s) & 1u) {
                    su[pj[s]] += delta;
                    v[s] -= delta;
                } else {
                    minv[s] -= delta;
                    mkey[s] = d2key(minv[s]) | pad;
                }
            }
            acc += delta;

            // single LDS.128: {u[sp[j1]], sp[j1]} — frozen during the run
            double2 ci = cinfo[j1];
            int i0n = (int)__double_as_longlong(ci.y);
            if (i0n == 0) { j0 = j1; break; }
            j0 = j1;
            i0 = i0n;
            // hoisted t for next iteration (off the LDS critical path)
            #pragma unroll
            for (int s = 0; s < 4; s++) t4[s] = ci.x + v[s];
        }

        // augment (serial, lane 0); write back u[i] once
        __syncwarp();
        if (lane == 0) {
            su[i]  = acc;
            sp[0]  = i;
            int jj = j0;
            while (jj) { int jn = sway[jj]; sp[jj] = sp[jn]; jj = jn; }
        }
        __syncwarp();

        // refresh cached {u,row} for used columns AND the break column j0
        #pragma unroll
        for (int s = 0; s < 4; s++) {
            int jj = jbase + s;
            if (((usedm >> s) & 1u) || (jj == j0)) {
                int r = sp[jj];
                cinfo[jj] = make_double2(su[r], __longlong_as_double((long long)r));
            }
        }
        __syncwarp();
    }

    for (int j = lane + 1; j <= NN; j += 32)
        g_col[b * NN + (sp[j] - 1)] = j - 1;
}

// ---------------------------------------------------------------------------
// Kernel 3: per-batch losses.
// ---------------------------------------------------------------------------
__global__ void loss_kernel(const float* __restrict__ bbox_pred,
                            const float* __restrict__ labels_pred,
                            const float* __restrict__ bbox_gt,
                            const int*   __restrict__ labels_gt)
{
    int b   = blockIdx.x;
    int tid = threadIdx.x;  // 128

    double nll_sum = 0.0, reg_sum = 0.0, giou_sum = 0.0;

    for (int q = tid; q < NN; q += blockDim.x) {
        int cg  = g_col[b * NN + q];
        int lab = labels_gt[b * NN + cg];

        const float* pr = labels_pred + (size_t)(b * NN + q) * CC;
        double se = 0.0;
        float  plab = 0.0f;
        for (int c = 0; c < CC; c++) {
            float pc = fminf(fmaxf(pr[c], 1e-7f), 1.0f - 1e-7f);
            se += (double)pc;
            if (c == lab) plab = pc;
        }
        nll_sum += log(se) - (double)logf(plab);

        float4 p = ((const float4*)bbox_pred)[b * NN + q];
        float4 t = ((const float4*)bbox_gt)[b * NN + cg];
        reg_sum += (double)(fabsf(p.x - t.x) + fabsf(p.y - t.y) +
                            fabsf(p.z - t.z) + fabsf(p.w - t.w));

        float4 g = ((const float4*)bbox_gt)[b * NN + q];
        float pulx = p.x - 0.5f * p.z, puly = p.y - 0.5f * p.w;
        float pdrx = p.x + 0.5f * p.z, pdry = p.y + 0.5f * p.w;
        float gulx = g.x - 0.5f * g.z, guly = g.y - 0.5f * g.w;
        float gdrx = g.x + 0.5f * g.z, gdry = g.y + 0.5f * g.w;
        float iw = fmaxf(fminf(pdrx, gdrx) - fmaxf(pulx, gulx) + 1.0f, 0.0f);
        float ih = fmaxf(fminf(pdry, gdry) - fmaxf(puly, guly) + 1.0f, 0.0f);
        float inter = iw * ih;
        float pw = fmaxf(pdrx - pulx + 1.0f, 0.0f);
        float ph = fmaxf(pdry - puly + 1.0f, 0.0f);
        float gw = fmaxf(gdrx - gulx + 1.0f, 0.0f);
        float gh = fmaxf(gdry - guly + 1.0f, 0.0f);
        float uni = pw * ph + gw * gh - inter;
        float iou = inter / fmaxf(uni, 1e-9f);
        float bw = fmaxf(fmaxf(pdrx, gdrx) - fminf(pulx, gulx) + 1.0f, 0.0f);
        float bh = fmaxf(fmaxf(pdry, gdry) - fminf(puly, guly) + 1.0f, 0.0f);
        float bound = bw * bh;
        float bgr = (bound - uni) / fmaxf(bound, 1e-9f);
        giou_sum += (double)(iou - bgr);
    }

    __shared__ double s0[128], s1[128], s2[128];
    s0[tid] = nll_sum; s1[tid] = reg_sum; s2[tid] = giou_sum;
    __syncthreads();
    for (int s = 64; s; s >>= 1) {
        if (tid < s) { s0[tid] += s0[tid + s]; s1[tid] += s1[tid + s]; s2[tid] += s2[tid + s]; }
        __syncthreads();
    }
    if (tid == 0) {
        double per = s0[0] / NN + 5.0 * (s1[0] / (NN * 4.0)) + 2.0 * (s2[0] / NN);
        g_partial[b] = per;
    }
}

__global__ void final_kernel(float* __restrict__ out)
{
    double s = 0.0;
    for (int b = 0; b < BB; b++) s += g_partial[b];
    out[0] = (float)s;
}

// ---------------------------------------------------------------------------
extern "C" void kernel_launch(void* const* d_in, const int* in_sizes, int n_in,
                              void* d_out, int out_size)
{
    const float* bbox_pred   = (const float*)d_in[0];
    const float* labels_pred = (const float*)d_in[1];
    const float* bbox_gt     = (const float*)d_in[2];
    const int*   labels_gt   = (const int*)d_in[3];

    cost_kernel<<<BB, 256>>>(bbox_pred, labels_pred, bbox_gt, labels_gt);
    hungarian_kernel<<<BB, 32>>>();
    loss_kernel<<<BB, 128>>>(bbox_pred, labels_pred, bbox_gt, labels_gt);
    final_kernel<<<1, 1>>>((float*)d_out);
}

// round 10
// speedup vs baseline: 7.9371x; 3.3797x over previous
#include <cuda_runtime.h>
#include <math.h>

#define BB 16
#define NN 100
#define CC 100

__device__ float  g_cost[BB * NN * NN];
__device__ int    g_col[BB * NN];
__device__ double g_partial[BB];

// ---------------------------------------------------------------------------
// Kernel 1: cost matrix, fp32 in the reference's exact op order.
// ---------------------------------------------------------------------------
__global__ void cost_kernel(const float* __restrict__ bbox_pred,
                            const float* __restrict__ labels_pred,
                            const float* __restrict__ bbox_gt,
                            const int*   __restrict__ labels_gt)
{
    int b = blockIdx.x;
    __shared__ float4 s_pr[NN];
    __shared__ float4 s_gt[NN];
    __shared__ int    s_lab[NN];
    for (int i = threadIdx.x; i < NN; i += blockDim.x) {
        s_pr[i]  = ((const float4*)bbox_pred)[b * NN + i];
        s_gt[i]  = ((const float4*)bbox_gt)[b * NN + i];
        s_lab[i] = labels_gt[b * NN + i];
    }
    __syncthreads();

    for (int idx = threadIdx.x; idx < NN * NN; idx += blockDim.x) {
        int q = idx / NN;
        int g = idx % NN;
        float4 p = s_pr[q];
        float4 t = s_gt[g];

        float pulx = p.x - 0.5f * p.z, puly = p.y - 0.5f * p.w;
        float pdrx = p.x + 0.5f * p.z, pdry = p.y + 0.5f * p.w;
        float gulx = t.x - 0.5f * t.z, guly = t.y - 0.5f * t.w;
        float gdrx = t.x + 0.5f * t.z, gdry = t.y + 0.5f * t.w;

        float iw = fmaxf(fminf(pdrx, gdrx) - fmaxf(pulx, gulx) + 1.0f, 0.0f);
        float ih = fmaxf(fminf(pdry, gdry) - fmaxf(puly, guly) + 1.0f, 0.0f);
        float inter = iw * ih;

        float pw = fmaxf(pdrx - pulx + 1.0f, 0.0f);
        float ph = fmaxf(pdry - puly + 1.0f, 0.0f);
        float gw = fmaxf(gdrx - gulx + 1.0f, 0.0f);
        float gh = fmaxf(gdry - guly + 1.0f, 0.0f);
        float uni = pw * ph + gw * gh - inter;
        float iou = inter / fmaxf(uni, 1e-9f);

        float bw = fmaxf(fmaxf(pdrx, gdrx) - fminf(pulx, gulx) + 1.0f, 0.0f);
        float bh = fmaxf(fmaxf(pdry, gdry) - fminf(puly, guly) + 1.0f, 0.0f);
        float bound = bw * bh;
        float bgr = (bound - uni) / fmaxf(bound, 1e-9f);

        float l1 = fabsf(p.x - t.x) + fabsf(p.y - t.y) +
                   fabsf(p.z - t.z) + fabsf(p.w - t.w);

        float prob = labels_pred[(b * NN + q) * CC + s_lab[g]];

        g_cost[(b * NN + q) * NN + g] = l1 - (iou - bgr) - prob;
    }
}

// ---------------------------------------------------------------------------
// fp32 sortable-key helpers: 32-bit key whose ordering == fp32 ordering.
// ---------------------------------------------------------------------------
__device__ __forceinline__ unsigned f2key(float f)
{
    int b = __float_as_int(f);
    return (unsigned)(b ^ ((b >> 31) | 0x80000000));
}
__device__ __forceinline__ float key2f(unsigned k)
{
    int kk = (int)k;
    return __int_as_float((kk < 0) ? (kk ^ 0x80000000) : ~kk);
}

// ---------------------------------------------------------------------------
// Kernel 2: JV Hungarian, one warp per batch, ALL-fp32 Dijkstra.
// vs R9: fp64 -> fp32 throughout the augmenting loop. Every dep-chain hop
// drops from DADD(47cy) to FADD(4cy), keys are 32-bit, delta is recovered
// exactly by inverting the winning key (no shfl), cinfo is one 64-bit LDS.
// The assignment (unique optimum, gaps ~1e-4 >> fp32 noise ~1e-6) -- and
// hence the loss -- is unchanged.
// ---------------------------------------------------------------------------
__global__ void __launch_bounds__(32, 1) hungarian_kernel()
{
    const int b    = blockIdx.x;
    const int lane = threadIdx.x;
    const unsigned FULL   = 0xffffffffu;
    const unsigned KMAX32 = 0xffffffffu;

    __shared__ float  sc[NN * NN];      // 40 KB cost
    __shared__ float  su[NN + 1];       // row duals
    __shared__ float2 cinfo[NN + 1];    // per column: .x = u[sp[j]], .y = bits(sp[j])
    __shared__ int    sp[NN + 1];       // column -> row
    __shared__ int    sway[NN + 1];     // augmenting-path predecessors
    __shared__ int    sargmin[NN + 1];  // column-reduction argmin rows
    __shared__ unsigned char srowass[NN + 1];  // greedy row-assigned flags

    const float* gc = g_cost + b * NN * NN;
    for (int t = lane; t < NN * NN; t += 32) sc[t] = gc[t];
    for (int j = lane; j <= NN; j += 32) {
        su[j] = 0.0f; sp[j] = 0; sway[j] = 0; srowass[j] = 0;
    }
    __syncwarp();

    const int jbase = 4 * lane + 1;
    const int coff  = (lane < 25) ? 4 * lane : 96;   // clamped float4 offset
    const unsigned pad = (lane < 25) ? 0u : KMAX32;  // key poison

    // ---- column reduction: v[j] = min_i c[i][j], first-argmin row ----
    float vminf[4] = {INFINITY, INFINITY, INFINITY, INFINITY};
    int   rmin[4]  = {1, 1, 1, 1};
    for (int r = 0; r < NN; r++) {
        float4 cf = *(const float4*)(sc + r * NN + coff);
        float cv[4] = {cf.x, cf.y, cf.z, cf.w};
        #pragma unroll
        for (int s = 0; s < 4; s++)
            if (cv[s] < vminf[s]) { vminf[s] = cv[s]; rmin[s] = r + 1; }
    }
    if (lane < 25) {
        #pragma unroll
        for (int s = 0; s < 4; s++) sargmin[jbase + s] = rmin[s];
    }
    __syncwarp();

    // ---- greedy assignment (serial, lane 0) ----
    if (lane == 0) {
        for (int j = 1; j <= NN; j++) {
            int r = sargmin[j];
            if (!srowass[r]) { srowass[r] = 1; sp[j] = r; }
        }
    }
    __syncwarp();
    if (lane < 25) {
        #pragma unroll
        for (int s = 0; s < 4; s++) {
            int jj = jbase + s;
            cinfo[jj] = make_float2(0.0f, __int_as_float(sp[jj]));
        }
    }
    __syncwarp();

    float v[4];
    #pragma unroll
    for (int s = 0; s < 4; s++) v[s] = vminf[s];

    // ---- augmenting Dijkstra (fp32) for unassigned rows only ----
    for (int i = 1; i <= NN; i++) {
        if (srowass[i]) continue;      // uniform branch (shared broadcast)

        float    minv[4];
        unsigned mkey[4];
        int      pj[4] = {0, 0, 0, 0};
        float    t4[4];
        #pragma unroll
        for (int s = 0; s < 4; s++) {
            minv[s] = INFINITY; mkey[s] = KMAX32;
            t4[s] = v[s];              // u[i] = 0 at insertion
        }
        unsigned usedm = 0;

        int   j0  = 0;
        int   i0  = i;
        float acc = 0.0f;              // running sum of deltas == u[i]

        while (true) {
            // mark used[j0] (only owner lane matches; never a padding lane)
            #pragma unroll
            for (int s = 0; s < 4; s++)
                if (j0 == jbase + s) { usedm |= 1u << s; mkey[s] = KMAX32; pj[s] = i0; }

            // scan: straight-line, predicated, all-fp32
            const float* crow = sc + (i0 - 1) * NN;
            float4 cf = *(const float4*)(crow + coff);
            float c[4] = {cf.x, cf.y, cf.z, cf.w};
            #pragma unroll
            for (int s = 0; s < 4; s++) {
                if (!((usedm >> s) & 1u)) {
                    float cur = c[s] - t4[s];           // t4 = u[i0] + v[s]
                    unsigned ck = f2key(cur) | pad;
                    if (ck < mkey[s]) { mkey[s] = ck; minv[s] = cur; sway[jbase + s] = j0; }
                }
            }
            // 2-level integer tournament, first-index on ties
            unsigned k01 = mkey[0]; int s01 = 0;
            if (mkey[1] < k01) { k01 = mkey[1]; s01 = 1; }
            unsigned k23 = mkey[2]; int s23 = 2;
            if (mkey[3] < k23) { k23 = mkey[3]; s23 = 3; }
            unsigned bkey = k01; int sb = s01;
            if (k23 < k01) { bkey = k23; sb = s23; }
            int bj = jbase + sb;

            // warp argmin: REDUX on 32-bit key (delta = exact inverse), then
            // REDUX on index among exact-key matchers (lowest-j tie-break)
            unsigned m1 = __reduce_min_sync(FULL, bkey);
            float delta = key2f(m1);
            unsigned jx = (bkey == m1) ? (unsigned)bj : 127u;
            int j1 = (int)__reduce_min_sync(FULL, jx);

            // dual updates (su addresses lane-owned; never padding lanes)
            #pragma unroll
            for (int s = 0; s < 4; s++) {
                if ((usedm >> s) & 1u) {
                    su[pj[s]] += delta;
                    v[s] -= delta;
                } else {
                    minv[s] -= delta;
                    mkey[s] = f2key(minv[s]) | pad;
                }
            }
            acc += delta;

            // single 64-bit LDS: {u[sp[j1]], sp[j1]} — frozen during the run
            float2 ci = cinfo[j1];
            int i0n = __float_as_int(ci.y);
            if (i0n == 0) { j0 = j1; break; }
            j0 = j1;
            i0 = i0n;
            // hoisted t for next iteration (off the LDS critical path)
            #pragma unroll
            for (int s = 0; s < 4; s++) t4[s] = ci.x + v[s];
        }

        // augment (serial, lane 0); write back u[i] once
        __syncwarp();
        if (lane == 0) {
            su[i]  = acc;
            sp[0]  = i;
            int jj = j0;
            while (jj) { int jn = sway[jj]; sp[jj] = sp[jn]; jj = jn; }
        }
        __syncwarp();

        // refresh cached {u,row} for used columns AND the break column j0
        #pragma unroll
        for (int s = 0; s < 4; s++) {
            int jj = jbase + s;
            if (((usedm >> s) & 1u) || (jj == j0)) {
                int r = sp[jj];
                cinfo[jj] = make_float2(su[r], __int_as_float(r));
            }
        }
        __syncwarp();
    }

    for (int j = lane + 1; j <= NN; j += 32)
        g_col[b * NN + (sp[j] - 1)] = j - 1;
}

// ---------------------------------------------------------------------------
// Kernel 3: per-batch losses.
// ---------------------------------------------------------------------------
__global__ void loss_kernel(const float* __restrict__ bbox_pred,
                            const float* __restrict__ labels_pred,
                            const float* __restrict__ bbox_gt,
                            const int*   __restrict__ labels_gt)
{
    int b   = blockIdx.x;
    int tid = threadIdx.x;  // 128

    double nll_sum = 0.0, reg_sum = 0.0, giou_sum = 0.0;

    for (int q = tid; q < NN; q += blockDim.x) {
        int cg  = g_col[b * NN + q];
        int lab = labels_gt[b * NN + cg];

        const float* pr = labels_pred + (size_t)(b * NN + q) * CC;
        double se = 0.0;
        float  plab = 0.0f;
        for (int c = 0; c < CC; c++) {
            float pc = fminf(fmaxf(pr[c], 1e-7f), 1.0f - 1e-7f);
            se += (double)pc;
            if (c == lab) plab = pc;
        }
        nll_sum += log(se) - (double)logf(plab);

        float4 p = ((const float4*)bbox_pred)[b * NN + q];
        float4 t = ((const float4*)bbox_gt)[b * NN + cg];
        reg_sum += (double)(fabsf(p.x - t.x) + fabsf(p.y - t.y) +
                            fabsf(p.z - t.z) + fabsf(p.w - t.w));

        float4 g = ((const float4*)bbox_gt)[b * NN + q];
        float pulx = p.x - 0.5f * p.z, puly = p.y - 0.5f * p.w;
        float pdrx = p.x + 0.5f * p.z, pdry = p.y + 0.5f * p.w;
        float gulx = g.x - 0.5f * g.z, guly = g.y - 0.5f * g.w;
        float gdrx = g.x + 0.5f * g.z, gdry = g.y + 0.5f * g.w;
        float iw = fmaxf(fminf(pdrx, gdrx) - fmaxf(pulx, gulx) + 1.0f, 0.0f);
        float ih = fmaxf(fminf(pdry, gdry) - fmaxf(puly, guly) + 1.0f, 0.0f);
        float inter = iw * ih;
        float pw = fmaxf(pdrx - pulx + 1.0f, 0.0f);
        float ph = fmaxf(pdry - puly + 1.0f, 0.0f);
        float gw = fmaxf(gdrx - gulx + 1.0f, 0.0f);
        float gh = fmaxf(gdry - guly + 1.0f, 0.0f);
        float uni = pw * ph + gw * gh - inter;
        float iou = inter / fmaxf(uni, 1e-9f);
        float bw = fmaxf(fmaxf(pdrx, gdrx) - fminf(pulx, gulx) + 1.0f, 0.0f);
        float bh = fmaxf(fmaxf(pdry, gdry) - fminf(puly, guly) + 1.0f, 0.0f);
        float bound = bw * bh;
        float bgr = (bound - uni) / fmaxf(bound, 1e-9f);
        giou_sum += (double)(iou - bgr);
    }

    __shared__ double s0[128], s1[128], s2[128];
    s0[tid] = nll_sum; s1[tid] = reg_sum; s2[tid] = giou_sum;
    __syncthreads();
    for (int s = 64; s; s >>= 1) {
        if (tid < s) { s0[tid] += s0[tid + s]; s1[tid] += s1[tid + s]; s2[tid] += s2[tid + s]; }
        __syncthreads();
    }
    if (tid == 0) {
        double per = s0[0] / NN + 5.0 * (s1[0] / (NN * 4.0)) + 2.0 * (s2[0] / NN);
        g_partial[b] = per;
    }
}

__global__ void final_kernel(float* __restrict__ out)
{
    double s = 0.0;
    for (int b = 0; b < BB; b++) s += g_partial[b];
    out[0] = (float)s;
}

// ---------------------------------------------------------------------------
extern "C" void kernel_launch(void* const* d_in, const int* in_sizes, int n_in,
                              void* d_out, int out_size)
{
    const float* bbox_pred   = (const float*)d_in[0];
    const float* labels_pred = (const float*)d_in[1];
    const float* bbox_gt     = (const float*)d_in[2];
    const int*   labels_gt   = (const int*)d_in[3];

    cost_kernel<<<BB, 256>>>(bbox_pred, labels_pred, bbox_gt, labels_gt);
    hungarian_kernel<<<BB, 32>>>();
    loss_kernel<<<BB, 128>>>(bbox_pred, labels_pred, bbox_gt, labels_gt);
    final_kernel<<<1, 1>>>((float*)d_out);
}